// round 9
// baseline (speedup 1.0000x reference)
#include <cuda_runtime.h>
#include <cuda_fp16.h>
#include <cuda_bf16.h>
#include <math.h>
#include <stdint.h>

#define D     128
#define NMAX  50000
#define EMAX  800000
#define NPAD  (NMAX + 128)
#define PS    68          // padded smem row stride (words)

// ---- scratch (device globals; zero at load; padded rows stay zero) ----
__device__ __align__(16) __half   g_T16[NPAD * D];      // GEMM out (fp16, unscaled)
__device__ __align__(16) uint32_t g_Xh[NPAD * 64];      // split input hi pairs (also A)
__device__ __align__(16) uint32_t g_Xl[NPAD * 64];      // split input lo pairs
__device__ __align__(16) uint32_t g_Whi[2 * 8192];      // packed W hi, [m][n][kp]
__device__ __align__(16) uint32_t g_Wlo[2 * 8192];
__device__ __align__(16) int g_cntPos[NMAX];   // atomic counters; MUST be 0 on entry (scan re-zeroes)
__device__ int   g_cnt[NMAX];                  // indeg (gather loop count)
__device__ int   g_rowptr[NMAX];
__device__ int   g_rank[EMAX];                 // within-destination rank of each edge
__device__ int   g_eidx[EMAX];                 // CSR source indices
__device__ float g_dinv[NMAX];
__device__ __align__(16) float g_gate[D];
__device__ __align__(16) float g_hbias[D];

// ---------------------------------------------------------------- bf16 split
__device__ __forceinline__ void split2f(float a, float b, uint32_t& hi, uint32_t& lo) {
    asm("cvt.rn.bf16x2.f32 %0, %1, %2;" : "=r"(hi) : "f"(b), "f"(a));
    float ha = __uint_as_float(hi << 16);
    float hb = __uint_as_float(hi & 0xffff0000u);
    float la = a - ha;
    float lb = b - hb;
    asm("cvt.rn.bf16x2.f32 %0, %1, %2;" : "=r"(lo) : "f"(lb), "f"(la));
}

// ---------------------------------------------------------------- K1: const + split + count/rank
// blocks [0,79]            : W split/pack (64) + hypernet gate/bias (16)
// blocks [80, 80+nbS)      : input split x -> g_Xh/g_Xl
// blocks [80+nbS, ...)     : edge count: rank[i] = atomicAdd(cnt[dst], 1)
__global__ void k_pre(const float* __restrict__ W1, const float* __restrict__ W2,
                      const float* __restrict__ ctx, const float* __restrict__ Wg,
                      const float* __restrict__ bg,  const float* __restrict__ Wb,
                      const float* __restrict__ X,
                      const int* __restrict__ edst,
                      int n, int E, int nbS) {
    int blk = blockIdx.x;
    int tid = threadIdx.x;
    if (blk < 64) {                                     // W split
        int idx = blk * 256 + tid;                      // 0..16383
        int m  = idx >> 13;
        int r  = idx & 8191;
        int nn = r & 127;
        int kp = r >> 7;
        const float* W = m ? W2 : W1;
        float w0 = W[(2 * kp) * D + nn];
        float w1 = W[(2 * kp + 1) * D + nn];
        uint32_t hi, lo;
        split2f(w0, w1, hi, lo);
        g_Whi[m * 8192 + nn * 64 + kp] = hi;
        g_Wlo[m * 8192 + nn * 64 + kp] = lo;
    } else if (blk < 80) {                              // hypernet
        int w    = (blk - 64) * 8 + (tid >> 5);
        int lane = tid & 31;
        float c0 = ctx[lane], c1 = ctx[lane + 32];
        float g = c0 * Wg[lane * D + w] + c1 * Wg[(lane + 32) * D + w];
        float b = c0 * Wb[lane * D + w] + c1 * Wb[(lane + 32) * D + w];
#pragma unroll
        for (int o = 16; o > 0; o >>= 1) {
            g += __shfl_down_sync(0xffffffffu, g, o);
            b += __shfl_down_sync(0xffffffffu, b, o);
        }
        if (lane == 0) {
            g_gate[w]  = 1.f / (1.f + __expf(-(g + bg[w])));
            g_hbias[w] = b;
        }
    } else if (blk < 80 + nbS) {                        // input split
        int i = (blk - 80) * 256 + tid;                 // float4 index
        if (i >= n * 32) return;
        float4 v = ((const float4*)X)[i];
        int row = i >> 5, c4 = i & 31;
        uint32_t h01, l01, h23, l23;
        split2f(v.x, v.y, h01, l01);
        split2f(v.z, v.w, h23, l23);
        *((uint2*)&g_Xh[(size_t)row * 64 + c4 * 2]) = make_uint2(h01, h23);
        *((uint2*)&g_Xl[(size_t)row * 64 + c4 * 2]) = make_uint2(l01, l23);
    } else {                                            // edge count + rank
        int i = (blk - 80 - nbS) * 256 + tid;
        if (i >= E) return;
        int d = edst[i];
        if ((unsigned)d < (unsigned)n)
            g_rank[i] = atomicAdd(&g_cntPos[d], 1);
    }
}

// ---------------------------------------------------------------- GEMM body (bf16x3 MMA)
__device__ __forceinline__ void mma16816(float* c, uint32_t a0, uint32_t a1,
                                         uint32_t a2, uint32_t a3,
                                         uint32_t b0, uint32_t b1) {
    asm volatile("mma.sync.aligned.m16n8k16.row.col.f32.bf16.bf16.f32 "
                 "{%0,%1,%2,%3}, {%4,%5,%6,%7}, {%8,%9}, {%0,%1,%2,%3};"
                 : "+f"(c[0]), "+f"(c[1]), "+f"(c[2]), "+f"(c[3])
                 : "r"(a0), "r"(a1), "r"(a2), "r"(a3), "r"(b0), "r"(b1));
}

__device__ void gemm_body(uint32_t* sm, int r0, int wsel, int n) {
    uint32_t* Xh = sm;
    uint32_t* Xl = Xh + 128 * PS;
    uint32_t* Wh = Xl + 128 * PS;
    uint32_t* Wl = Wh + 128 * PS;
    int tid = threadIdx.x;

    const uint32_t* gwh = g_Whi + wsel * 8192;
    const uint32_t* gwl = g_Wlo + wsel * 8192;
#pragma unroll
    for (int i = 0; i < 8; i++) {
        int q  = tid + i * 256;
        int wb = q * 4;
        int nn = wb >> 6, kp = wb & 63;
        *((uint4*)&Wh[nn * PS + kp]) = ((const uint4*)gwh)[q];
        *((uint4*)&Wl[nn * PS + kp]) = ((const uint4*)gwl)[q];
    }
    const uint4* gxh = (const uint4*)g_Xh + (size_t)r0 * 16;
    const uint4* gxl = (const uint4*)g_Xl + (size_t)r0 * 16;
#pragma unroll
    for (int i = 0; i < 8; i++) {
        int q   = tid + i * 256;
        int row = q >> 4, k4 = q & 15;
        *((uint4*)&Xh[row * PS + k4 * 4]) = gxh[q];
        *((uint4*)&Xl[row * PS + k4 * 4]) = gxl[q];
    }
    __syncthreads();

    int wid  = tid >> 5;
    int lane = tid & 31;
    int g    = lane >> 2;
    int tig  = lane & 3;
    int rA   = wid * 16 + g;

    float acc[16][4];
#pragma unroll
    for (int t = 0; t < 16; t++)
#pragma unroll
        for (int c = 0; c < 4; c++) acc[t][c] = 0.f;

#pragma unroll
    for (int s = 0; s < 8; s++) {
        int kp = s * 8;
        uint32_t ah0 = Xh[rA * PS + kp + tig];
        uint32_t ah1 = Xh[(rA + 8) * PS + kp + tig];
        uint32_t ah2 = Xh[rA * PS + kp + tig + 4];
        uint32_t ah3 = Xh[(rA + 8) * PS + kp + tig + 4];
        uint32_t al0 = Xl[rA * PS + kp + tig];
        uint32_t al1 = Xl[(rA + 8) * PS + kp + tig];
        uint32_t al2 = Xl[rA * PS + kp + tig + 4];
        uint32_t al3 = Xl[(rA + 8) * PS + kp + tig + 4];
#pragma unroll
        for (int nt = 0; nt < 16; nt++) {
            int nb = nt * 8 + g;
            uint32_t bh0 = Wh[nb * PS + kp + tig];
            uint32_t bh1 = Wh[nb * PS + kp + tig + 4];
            uint32_t bl0 = Wl[nb * PS + kp + tig];
            uint32_t bl1 = Wl[nb * PS + kp + tig + 4];
            mma16816(acc[nt], ah0, ah1, ah2, ah3, bh0, bh1);
            mma16816(acc[nt], ah0, ah1, ah2, ah3, bl0, bl1);
            mma16816(acc[nt], al0, al1, al2, al3, bh0, bh1);
        }
    }

    int gr0 = r0 + wid * 16 + g;
    int gr1 = gr0 + 8;
#pragma unroll
    for (int nt = 0; nt < 16; nt++) {
        int c = nt * 8 + 2 * tig;
        if (gr0 < n)
            *((__half2*)&g_T16[(size_t)gr0 * D + c]) =
                __floats2half2_rn(acc[nt][0], acc[nt][1]);
        if (gr1 < n)
            *((__half2*)&g_T16[(size_t)gr1 * D + c]) =
                __floats2half2_rn(acc[nt][2], acc[nt][3]);
    }
}

// ---------------------------------------------------------------- K2: scan (block 0) || GEMM1 (blocks 1..)
__global__ void __launch_bounds__(256)
k_scan_gemm(int n) {
    extern __shared__ uint32_t sm[];
    if (blockIdx.x != 0) {
        gemm_body(sm, (blockIdx.x - 1) * 128, 0, n);
        return;
    }
    // ---- scan: rowptr/cnt/dinv from g_cntPos; re-zero counters ----
    __shared__ int part[256];
    int tid = threadIdx.x;
    const int per = 196;                    // 256*196 >= 50000, %4==0
    int base = tid * per;
    int s = 0;
    for (int i = 0; i < per; i += 4) {
        int r = base + i;
        if (r + 3 < n) {
            int4 v = *((const int4*)&g_cntPos[r]);
            s += v.x + v.y + v.z + v.w;
        } else {
#pragma unroll
            for (int u = 0; u < 4; u++)
                if (r + u < n) s += g_cntPos[r + u];
        }
    }
    part[tid] = s;
    __syncthreads();
    for (int off = 1; off < 256; off <<= 1) {
        int v = (tid >= off) ? part[tid - off] : 0;
        __syncthreads();
        part[tid] += v;
        __syncthreads();
    }
    int run = (tid == 0) ? 0 : part[tid - 1];
    for (int i = 0; i < per; i += 4) {
        int r = base + i;
        if (r >= n) break;
        int4 v;
        if (r + 3 < n) v = *((const int4*)&g_cntPos[r]);
        else {
            v.x = (r     < n) ? g_cntPos[r]     : 0;
            v.y = (r + 1 < n) ? g_cntPos[r + 1] : 0;
            v.z = (r + 2 < n) ? g_cntPos[r + 2] : 0;
            v.w = (r + 3 < n) ? g_cntPos[r + 3] : 0;
        }
        int cv[4] = {v.x, v.y, v.z, v.w};
#pragma unroll
        for (int u = 0; u < 4; u++) {
            int rr = r + u;
            if (rr < n) {
                g_rowptr[rr] = run;
                g_cnt[rr]    = cv[u];
                run += cv[u];
                g_dinv[rr]   = rsqrtf((float)(cv[u] + 1));
                g_cntPos[rr] = 0;           // restore invariant for next call
            }
        }
    }
}

// ---------------------------------------------------------------- standalone GEMM (conv2)
__global__ void __launch_bounds__(256)
k_gemm(int wsel, int n) {
    extern __shared__ uint32_t sm[];
    gemm_body(sm, blockIdx.x * 128, wsel, n);
}

// ---------------------------------------------------------------- K3: atomic-free CSR placement
__global__ void k_place(const int* __restrict__ esrc,
                        const int* __restrict__ edst, int E, int n) {
    int i = blockIdx.x * blockDim.x + threadIdx.x;
    if (i >= E) return;
    int s = esrc[i];
    int d = edst[i];
    if ((unsigned)s >= (unsigned)n || (unsigned)d >= (unsigned)n) return;
    g_eidx[g_rowptr[d] + g_rank[i]] = s;
}

// ---------------------------------------------------------------- fused gather + epilogue (fp16 T)
// out[d] = epi( dinv[d] * ( dinv[d]*T[d] + sum_s dinv[s]*T[s] ) + b )
__device__ __forceinline__ float4 up4(uint2 v) {
    float2 a = __half22float2(*(__half2*)&v.x);
    float2 b = __half22float2(*(__half2*)&v.y);
    return make_float4(a.x, a.y, b.x, b.y);
}

template <int MODE>
__global__ void k_gather(float* __restrict__ Out,
                         const float* __restrict__ bvec, int n) {
    int w = (blockIdx.x * blockDim.x + threadIdx.x) >> 5;
    if (w >= n) return;
    int lane = threadIdx.x & 31;
    int beg = g_rowptr[w];
    int cnt = g_cnt[w];
    float di = g_dinv[w];

    float4 acc[8];
    {   // self term: dinv[w] * T[w]
        uint2 sv = ((const uint2*)(g_T16 + (size_t)w * D))[lane];
        float4 f = up4(sv);
        acc[0] = make_float4(di * f.x, di * f.y, di * f.z, di * f.w);
    }
#pragma unroll
    for (int u = 1; u < 8; u++) acc[u] = make_float4(0.f, 0.f, 0.f, 0.f);

    int j = 0;
    while (j < cnt) {
        int chunk = min(cnt - j, 32);
        int   myidx = 0;
        float mydnv = 0.f;
        if (lane < chunk) {
            myidx = g_eidx[beg + j + lane];
            mydnv = g_dinv[myidx];
        }
        int t = 0;
        for (; t + 7 < chunk; t += 8) {
#pragma unroll
            for (int u = 0; u < 8; u++) {
                int   s  = __shfl_sync(0xffffffffu, myidx, t + u);
                float ds = __shfl_sync(0xffffffffu, mydnv, t + u);
                uint2 v  = ((const uint2*)(g_T16 + (size_t)s * D))[lane];
                float4 f = up4(v);
                acc[u].x += ds * f.x; acc[u].y += ds * f.y;
                acc[u].z += ds * f.z; acc[u].w += ds * f.w;
            }
        }
        for (; t < chunk; t++) {
            int   s  = __shfl_sync(0xffffffffu, myidx, t);
            float ds = __shfl_sync(0xffffffffu, mydnv, t);
            uint2 v  = ((const uint2*)(g_T16 + (size_t)s * D))[lane];
            float4 f = up4(v);
            acc[0].x += ds * f.x; acc[0].y += ds * f.y;
            acc[0].z += ds * f.z; acc[0].w += ds * f.w;
        }
        j += chunk;
    }
#pragma unroll
    for (int u = 1; u < 8; u++) {
        acc[0].x += acc[u].x; acc[0].y += acc[u].y;
        acc[0].z += acc[u].z; acc[0].w += acc[u].w;
    }

    float4 b = ((const float4*)bvec)[lane];
    float4 o;
    o.x = acc[0].x * di + b.x;
    o.y = acc[0].y * di + b.y;
    o.z = acc[0].z * di + b.z;
    o.w = acc[0].w * di + b.w;
    if (MODE == 1) {
        o.x = o.x > 0.f ? o.x : 0.2f * o.x;
        o.y = o.y > 0.f ? o.y : 0.2f * o.y;
        o.z = o.z > 0.f ? o.z : 0.2f * o.z;
        o.w = o.w > 0.f ? o.w : 0.2f * o.w;
        uint32_t h01, l01, h23, l23;
        split2f(o.x, o.y, h01, l01);
        split2f(o.z, o.w, h23, l23);
        *((uint2*)&g_Xh[(size_t)w * 64 + lane * 2]) = make_uint2(h01, h23);
        *((uint2*)&g_Xl[(size_t)w * 64 + lane * 2]) = make_uint2(l01, l23);
    } else {
        float4 gt = ((const float4*)g_gate)[lane];
        float4 hb = ((const float4*)g_hbias)[lane];
        o.x = o.x * gt.x + hb.x;
        o.y = o.y * gt.y + hb.y;
        o.z = o.z * gt.z + hb.z;
        o.w = o.w * gt.w + hb.w;
        ((float4*)(Out + (size_t)w * D))[lane] = o;
    }
}

// ----------------------------------------------------------------
extern "C" void kernel_launch(void* const* d_in, const int* in_sizes, int n_in,
                              void* d_out, int out_size) {
    const float* x    = (const float*)d_in[0];
    const float* ctx  = (const float*)d_in[1];
    const float* W1   = (const float*)d_in[2];
    const float* b1   = (const float*)d_in[3];
    const float* W2   = (const float*)d_in[4];
    const float* b2   = (const float*)d_in[5];
    const float* Wg   = (const float*)d_in[6];
    const float* bg   = (const float*)d_in[7];
    const float* Wb   = (const float*)d_in[8];
    const int*   ei   = (const int*)d_in[9];     // int32 (JAX x64 disabled)
    float*       out  = (float*)d_out;

    int N = in_sizes[0] / D;
    int E = in_sizes[9] / 2;
    const int* esrc = ei;
    const int* edst = ei + E;

    int smemG = 4 * 128 * PS * sizeof(uint32_t);          // 139264 B
    cudaFuncSetAttribute(k_scan_gemm,
                         cudaFuncAttributeMaxDynamicSharedMemorySize, smemG);
    cudaFuncSetAttribute(k_gemm,
                         cudaFuncAttributeMaxDynamicSharedMemorySize, smemG);

    int nbS  = (N * 32 + 255) / 256;              // split blocks
    int nbE  = (E + 255) / 256;                   // edge blocks
    int gblk = (N + 127) / 128;                   // gemm blocks
    long long gth = (long long)N * 32;            // one warp per node
    int nbG  = (int)((gth + 255) / 256);

    // K1: W-split + hypernet + input-split + edge count/rank (all independent)
    k_pre<<<80 + nbS + nbE, 256>>>(W1, W2, ctx, Wg, bg, Wb, x, edst, N, E, nbS);

    // K2: scan (block 0) || GEMM1 (blocks 1..gblk)
    k_scan_gemm<<<1 + gblk, 256, smemG>>>(N);

    // K3: atomic-free CSR placement
    k_place<<<nbE, 256>>>(esrc, edst, E, N);

    // K4: conv1 gather -> A (split bf16)
    k_gather<1><<<nbG, 256>>>(nullptr, b1, N);

    // K5: GEMM2
    k_gemm<<<gblk, 256, smemG>>>(1, N);

    // K6: conv2 gather -> out
    k_gather<2><<<nbG, 256>>>(out, b2, N);
}

// round 11
// speedup vs baseline: 1.0726x; 1.0726x over previous
#include <cuda_runtime.h>
#include <cuda_bf16.h>
#include <math.h>
#include <stdint.h>

#define D     128
#define NMAX  50000
#define EMAX  800000
#define NPAD  (NMAX + 128)
#define PS    68          // padded smem row stride (words)

// ---- scratch (device globals; zero at load) ----
__device__ __align__(16) float    g_T[NPAD * D];        // GEMM out (fp32)
__device__ __align__(16) uint32_t g_Xh[NPAD * 64];      // split input hi pairs (also A)
__device__ __align__(16) uint32_t g_Xl[NPAD * 64];      // split input lo pairs
__device__ __align__(16) uint32_t g_Whi[2 * 8192];      // packed W hi, [m][n][kp]
__device__ __align__(16) uint32_t g_Wlo[2 * 8192];
__device__ __align__(16) int g_cntPos[NMAX];   // atomic counters; 0 on entry (scan re-zeroes)
__device__ int   g_cnt[NMAX];                  // indeg
__device__ int   g_rowptr[NMAX];
__device__ int   g_rank[EMAX];                 // within-destination rank
__device__ int   g_eidx[EMAX];                 // CSR source indices
__device__ float g_dinv[NMAX];
__device__ __align__(16) float g_gate[D];
__device__ __align__(16) float g_hbias[D];

// ---------------------------------------------------------------- helpers
__device__ __forceinline__ void split2f(float a, float b, uint32_t& hi, uint32_t& lo) {
    asm("cvt.rn.bf16x2.f32 %0, %1, %2;" : "=r"(hi) : "f"(b), "f"(a));
    float ha = __uint_as_float(hi << 16);
    float hb = __uint_as_float(hi & 0xffff0000u);
    float la = a - ha;
    float lb = b - hb;
    asm("cvt.rn.bf16x2.f32 %0, %1, %2;" : "=r"(lo) : "f"(lb), "f"(la));
}
__device__ __forceinline__ uint64_t add2(uint64_t a, uint64_t b) {
    uint64_t d;
    asm("add.rn.f32x2 %0, %1, %2;" : "=l"(d) : "l"(a), "l"(b));
    return d;
}
__device__ __forceinline__ float2 unpk(uint64_t u) {
    float lo, hi;
    asm("mov.b64 {%0, %1}, %2;" : "=f"(lo), "=f"(hi) : "l"(u));
    return make_float2(lo, hi);
}

// ---------------------------------------------------------------- K1: const + split + count/rank
__global__ void k_pre(const float* __restrict__ W1, const float* __restrict__ W2,
                      const float* __restrict__ ctx, const float* __restrict__ Wg,
                      const float* __restrict__ bg,  const float* __restrict__ Wb,
                      const float* __restrict__ X,
                      const int* __restrict__ edst,
                      int n, int E, int nbS) {
    int blk = blockIdx.x;
    int tid = threadIdx.x;
    if (blk < 64) {                                     // W split/pack/transpose
        int idx = blk * 256 + tid;                      // 0..16383
        int m  = idx >> 13;
        int r  = idx & 8191;
        int nn = r & 127;
        int kp = r >> 7;
        const float* W = m ? W2 : W1;
        float w0 = W[(2 * kp) * D + nn];
        float w1 = W[(2 * kp + 1) * D + nn];
        uint32_t hi, lo;
        split2f(w0, w1, hi, lo);
        g_Whi[m * 8192 + nn * 64 + kp] = hi;
        g_Wlo[m * 8192 + nn * 64 + kp] = lo;
    } else if (blk < 80) {                              // hypernet
        int w    = (blk - 64) * 8 + (tid >> 5);
        int lane = tid & 31;
        float c0 = ctx[lane], c1 = ctx[lane + 32];
        float g = c0 * Wg[lane * D + w] + c1 * Wg[(lane + 32) * D + w];
        float b = c0 * Wb[lane * D + w] + c1 * Wb[(lane + 32) * D + w];
#pragma unroll
        for (int o = 16; o > 0; o >>= 1) {
            g += __shfl_down_sync(0xffffffffu, g, o);
            b += __shfl_down_sync(0xffffffffu, b, o);
        }
        if (lane == 0) {
            g_gate[w]  = 1.f / (1.f + __expf(-(g + bg[w])));
            g_hbias[w] = b;
        }
    } else if (blk < 80 + nbS) {                        // input split
        int i = (blk - 80) * 256 + tid;                 // float4 index
        if (i >= n * 32) return;
        float4 v = ((const float4*)X)[i];
        int row = i >> 5, c4 = i & 31;
        uint32_t h01, l01, h23, l23;
        split2f(v.x, v.y, h01, l01);
        split2f(v.z, v.w, h23, l23);
        *((uint2*)&g_Xh[(size_t)row * 64 + c4 * 2]) = make_uint2(h01, h23);
        *((uint2*)&g_Xl[(size_t)row * 64 + c4 * 2]) = make_uint2(l01, l23);
    } else {                                            // edge count + rank
        int i = (blk - 80 - nbS) * 256 + tid;
        if (i >= E) return;
        int d = edst[i];
        if ((unsigned)d < (unsigned)n)
            g_rank[i] = atomicAdd(&g_cntPos[d], 1);
    }
}

// ---------------------------------------------------------------- GEMM body (bf16x3 MMA)
__device__ __forceinline__ void mma16816(float* c, uint32_t a0, uint32_t a1,
                                         uint32_t a2, uint32_t a3,
                                         uint32_t b0, uint32_t b1) {
    asm volatile("mma.sync.aligned.m16n8k16.row.col.f32.bf16.bf16.f32 "
                 "{%0,%1,%2,%3}, {%4,%5,%6,%7}, {%8,%9}, {%0,%1,%2,%3};"
                 : "+f"(c[0]), "+f"(c[1]), "+f"(c[2]), "+f"(c[3])
                 : "r"(a0), "r"(a1), "r"(a2), "r"(a3), "r"(b0), "r"(b1));
}

// scale=0: store raw; scale=1: multiply rows by g_dinv
__device__ void gemm_body(uint32_t* sm, int r0, int wsel, int scale, int n) {
    uint32_t* Xh = sm;
    uint32_t* Xl = Xh + 128 * PS;
    uint32_t* Wh = Xl + 128 * PS;
    uint32_t* Wl = Wh + 128 * PS;
    int tid = threadIdx.x;

    const uint32_t* gwh = g_Whi + wsel * 8192;
    const uint32_t* gwl = g_Wlo + wsel * 8192;
#pragma unroll
    for (int i = 0; i < 8; i++) {
        int q  = tid + i * 256;
        int wb = q * 4;
        int nn = wb >> 6, kp = wb & 63;
        *((uint4*)&Wh[nn * PS + kp]) = ((const uint4*)gwh)[q];
        *((uint4*)&Wl[nn * PS + kp]) = ((const uint4*)gwl)[q];
    }
    const uint4* gxh = (const uint4*)g_Xh + (size_t)r0 * 16;
    const uint4* gxl = (const uint4*)g_Xl + (size_t)r0 * 16;
#pragma unroll
    for (int i = 0; i < 8; i++) {
        int q   = tid + i * 256;
        int row = q >> 4, k4 = q & 15;
        *((uint4*)&Xh[row * PS + k4 * 4]) = gxh[q];
        *((uint4*)&Xl[row * PS + k4 * 4]) = gxl[q];
    }
    __syncthreads();

    int wid  = tid >> 5;
    int lane = tid & 31;
    int g    = lane >> 2;
    int tig  = lane & 3;
    int rA   = wid * 16 + g;

    float acc[16][4];
#pragma unroll
    for (int t = 0; t < 16; t++)
#pragma unroll
        for (int c = 0; c < 4; c++) acc[t][c] = 0.f;

#pragma unroll
    for (int s = 0; s < 8; s++) {
        int kp = s * 8;
        uint32_t ah0 = Xh[rA * PS + kp + tig];
        uint32_t ah1 = Xh[(rA + 8) * PS + kp + tig];
        uint32_t ah2 = Xh[rA * PS + kp + tig + 4];
        uint32_t ah3 = Xh[(rA + 8) * PS + kp + tig + 4];
        uint32_t al0 = Xl[rA * PS + kp + tig];
        uint32_t al1 = Xl[(rA + 8) * PS + kp + tig];
        uint32_t al2 = Xl[rA * PS + kp + tig + 4];
        uint32_t al3 = Xl[(rA + 8) * PS + kp + tig + 4];
#pragma unroll
        for (int nt = 0; nt < 16; nt++) {
            int nb = nt * 8 + g;
            uint32_t bh0 = Wh[nb * PS + kp + tig];
            uint32_t bh1 = Wh[nb * PS + kp + tig + 4];
            uint32_t bl0 = Wl[nb * PS + kp + tig];
            uint32_t bl1 = Wl[nb * PS + kp + tig + 4];
            mma16816(acc[nt], ah0, ah1, ah2, ah3, bh0, bh1);
            mma16816(acc[nt], ah0, ah1, ah2, ah3, bl0, bl1);
            mma16816(acc[nt], al0, al1, al2, al3, bh0, bh1);
        }
    }

    int gr0 = r0 + wid * 16 + g;
    int gr1 = gr0 + 8;
    float d0 = 1.f, d1 = 1.f;
    if (scale) {
        d0 = (gr0 < n) ? g_dinv[gr0] : 0.f;
        d1 = (gr1 < n) ? g_dinv[gr1] : 0.f;
    }
#pragma unroll
    for (int nt = 0; nt < 16; nt++) {
        int c = nt * 8 + 2 * tig;
        if (gr0 < n)
            *((float2*)&g_T[(size_t)gr0 * D + c]) =
                make_float2(acc[nt][0] * d0, acc[nt][1] * d0);
        if (gr1 < n)
            *((float2*)&g_T[(size_t)gr1 * D + c]) =
                make_float2(acc[nt][2] * d1, acc[nt][3] * d1);
    }
}

// ---------------------------------------------------------------- K2: scan (block 0) || GEMM1 (unscaled)
__global__ void __launch_bounds__(256)
k_scan_gemm(int n) {
    extern __shared__ uint32_t sm[];
    if (blockIdx.x != 0) {
        gemm_body(sm, (blockIdx.x - 1) * 128, 0, /*scale=*/0, n);
        return;
    }
    __shared__ int part[256];
    int tid = threadIdx.x;
    const int per = 196;                    // 256*196 >= 50000, %4==0
    int base = tid * per;
    int s = 0;
    for (int i = 0; i < per; i += 4) {
        int r = base + i;
        if (r + 3 < n) {
            int4 v = *((const int4*)&g_cntPos[r]);
            s += v.x + v.y + v.z + v.w;
        } else {
#pragma unroll
            for (int u = 0; u < 4; u++)
                if (r + u < n) s += g_cntPos[r + u];
        }
    }
    part[tid] = s;
    __syncthreads();
    for (int off = 1; off < 256; off <<= 1) {
        int v = (tid >= off) ? part[tid - off] : 0;
        __syncthreads();
        part[tid] += v;
        __syncthreads();
    }
    int run = (tid == 0) ? 0 : part[tid - 1];
    for (int i = 0; i < per; i += 4) {
        int r = base + i;
        if (r >= n) break;
        int4 v;
        if (r + 3 < n) v = *((const int4*)&g_cntPos[r]);
        else {
            v.x = (r     < n) ? g_cntPos[r]     : 0;
            v.y = (r + 1 < n) ? g_cntPos[r + 1] : 0;
            v.z = (r + 2 < n) ? g_cntPos[r + 2] : 0;
            v.w = (r + 3 < n) ? g_cntPos[r + 3] : 0;
        }
        int cv[4] = {v.x, v.y, v.z, v.w};
#pragma unroll
        for (int u = 0; u < 4; u++) {
            int rr = r + u;
            if (rr < n) {
                g_rowptr[rr] = run;
                g_cnt[rr]    = cv[u];
                run += cv[u];
                g_dinv[rr]   = rsqrtf((float)(cv[u] + 1));
                g_cntPos[rr] = 0;           // restore invariant
            }
        }
    }
}

// ---------------------------------------------------------------- standalone GEMM (conv2, prescaled)
__global__ void __launch_bounds__(256)
k_gemm(int wsel, int n) {
    extern __shared__ uint32_t sm[];
    gemm_body(sm, blockIdx.x * 128, wsel, /*scale=*/1, n);
}

// ---------------------------------------------------------------- K3: CSR place + T prescale (conv1)
__global__ void k_place_scale(const int* __restrict__ esrc,
                              const int* __restrict__ edst,
                              int E, int n, int nbE) {
    int blk = blockIdx.x;
    int tid = threadIdx.x;
    if (blk < nbE) {
        int i = blk * 256 + tid;
        if (i >= E) return;
        int s = esrc[i];
        int d = edst[i];
        if ((unsigned)s >= (unsigned)n || (unsigned)d >= (unsigned)n) return;
        g_eidx[g_rowptr[d] + g_rank[i]] = s;
    } else {
        int i = (blk - nbE) * 256 + tid;        // float4 index
        if (i >= n * 32) return;
        float di = g_dinv[i >> 5];
        float4 v = ((const float4*)g_T)[i];
        v.x *= di; v.y *= di; v.z *= di; v.w *= di;
        ((float4*)g_T)[i] = v;
    }
}

// ---------------------------------------------------------------- fused gather + epilogue (fp32 T, pure ADD)
// T rows are prescaled: out[d] = epi( dinv[d] * sum_{s in d+in(d)} T[s] + b )
template <int MODE>
__global__ void __launch_bounds__(256, 5)
k_gather(float* __restrict__ Out, const float* __restrict__ bvec, int n) {
    int w = (blockIdx.x * blockDim.x + threadIdx.x) >> 5;
    if (w >= n) return;
    int lane = threadIdx.x & 31;
    int beg = g_rowptr[w];
    int cnt = g_cnt[w];
    const ulonglong2* Tv = (const ulonglong2*)g_T;   // 32 per row; lane -> one

    uint64_t a0, a1, a2, a3, a4, a5, a6, a7;
    {
        ulonglong2 sv = Tv[(size_t)w * 32 + lane];   // self term
        a0 = sv.x; a1 = sv.y;
    }
    a2 = a3 = a4 = a5 = a6 = a7 = 0ull;

    int j = 0;
    while (j < cnt) {
        int chunk = min(cnt - j, 32);
        int myidx = (lane < chunk) ? g_eidx[beg + j + lane] : 0;
        int t = 0;
        for (; t + 3 < chunk; t += 4) {
            int s0 = __shfl_sync(0xffffffffu, myidx, t);
            int s1 = __shfl_sync(0xffffffffu, myidx, t + 1);
            int s2 = __shfl_sync(0xffffffffu, myidx, t + 2);
            int s3 = __shfl_sync(0xffffffffu, myidx, t + 3);
            ulonglong2 v0 = Tv[(size_t)s0 * 32 + lane];
            ulonglong2 v1 = Tv[(size_t)s1 * 32 + lane];
            ulonglong2 v2 = Tv[(size_t)s2 * 32 + lane];
            ulonglong2 v3 = Tv[(size_t)s3 * 32 + lane];
            a0 = add2(a0, v0.x); a1 = add2(a1, v0.y);
            a2 = add2(a2, v1.x); a3 = add2(a3, v1.y);
            a4 = add2(a4, v2.x); a5 = add2(a5, v2.y);
            a6 = add2(a6, v3.x); a7 = add2(a7, v3.y);
        }
        for (; t < chunk; t++) {
            int s0 = __shfl_sync(0xffffffffu, myidx, t);
            ulonglong2 v0 = Tv[(size_t)s0 * 32 + lane];
            a0 = add2(a0, v0.x); a1 = add2(a1, v0.y);
        }
        j += chunk;
    }
    a0 = add2(add2(a0, a2), add2(a4, a6));
    a1 = add2(add2(a1, a3), add2(a5, a7));

    float2 lo = unpk(a0);
    float2 hi = unpk(a1);
    float di = g_dinv[w];
    float4 b = ((const float4*)bvec)[lane];
    float4 o;
    o.x = lo.x * di + b.x;
    o.y = lo.y * di + b.y;
    o.z = hi.x * di + b.z;
    o.w = hi.y * di + b.w;
    if (MODE == 1) {
        o.x = o.x > 0.f ? o.x : 0.2f * o.x;
        o.y = o.y > 0.f ? o.y : 0.2f * o.y;
        o.z = o.z > 0.f ? o.z : 0.2f * o.z;
        o.w = o.w > 0.f ? o.w : 0.2f * o.w;
        uint32_t h01, l01, h23, l23;
        split2f(o.x, o.y, h01, l01);
        split2f(o.z, o.w, h23, l23);
        *((uint2*)&g_Xh[(size_t)w * 64 + lane * 2]) = make_uint2(h01, h23);
        *((uint2*)&g_Xl[(size_t)w * 64 + lane * 2]) = make_uint2(l01, l23);
    } else {
        float4 gt = ((const float4*)g_gate)[lane];
        float4 hb = ((const float4*)g_hbias)[lane];
        o.x = o.x * gt.x + hb.x;
        o.y = o.y * gt.y + hb.y;
        o.z = o.z * gt.z + hb.z;
        o.w = o.w * gt.w + hb.w;
        ((float4*)(Out + (size_t)w * D))[lane] = o;
    }
}

// ----------------------------------------------------------------
extern "C" void kernel_launch(void* const* d_in, const int* in_sizes, int n_in,
                              void* d_out, int out_size) {
    const float* x    = (const float*)d_in[0];
    const float* ctx  = (const float*)d_in[1];
    const float* W1   = (const float*)d_in[2];
    const float* b1   = (const float*)d_in[3];
    const float* W2   = (const float*)d_in[4];
    const float* b2   = (const float*)d_in[5];
    const float* Wg   = (const float*)d_in[6];
    const float* bg   = (const float*)d_in[7];
    const float* Wb   = (const float*)d_in[8];
    const int*   ei   = (const int*)d_in[9];     // int32 (JAX x64 disabled)
    float*       out  = (float*)d_out;

    int N = in_sizes[0] / D;
    int E = in_sizes[9] / 2;
    const int* esrc = ei;
    const int* edst = ei + E;

    int smemG = 4 * 128 * PS * sizeof(uint32_t);          // 139264 B
    cudaFuncSetAttribute(k_scan_gemm,
                         cudaFuncAttributeMaxDynamicSharedMemorySize, smemG);
    cudaFuncSetAttribute(k_gemm,
                         cudaFuncAttributeMaxDynamicSharedMemorySize, smemG);

    int nbS  = (N * 32 + 255) / 256;              // N*32 float4-threads
    int nbE  = (E + 255) / 256;
    int gblk = (N + 127) / 128;
    long long gth = (long long)N * 32;
    int nbG  = (int)((gth + 255) / 256);

    // K1: const + input split + edge count/rank
    k_pre<<<80 + nbS + nbE, 256>>>(W1, W2, ctx, Wg, bg, Wb, x, edst, N, E, nbS);

    // K2: scan (block 0) || GEMM1 unscaled
    k_scan_gemm<<<1 + gblk, 256, smemG>>>(N);

    // K3: CSR place || T *= dinv
    k_place_scale<<<nbE + nbS, 256>>>(esrc, edst, E, N, nbE);

    // K4: conv1 gather -> A (split bf16)
    k_gather<1><<<nbG, 256>>>(nullptr, b1, N);

    // K5: GEMM2 (prescaled)
    k_gemm<<<gblk, 256, smemG>>>(1, N);

    // K6: conv2 gather -> out
    k_gather<2><<<nbG, 256>>>(out, b2, N);
}

// round 13
// speedup vs baseline: 1.3231x; 1.2335x over previous
#include <cuda_runtime.h>
#include <cuda_fp16.h>
#include <cuda_bf16.h>
#include <math.h>
#include <stdint.h>

#define D     128
#define NMAX  50000
#define EMAX  800000
#define NPAD  (NMAX + 128)
#define PS    68          // padded smem row stride (words)

// ---- scratch (device globals; zero at load) ----
__device__ __align__(16) __half   g_T16[NPAD * D];      // message table (fp16, prescaled)
__device__ __align__(16) uint32_t g_Xh[NPAD * 64];      // split input hi pairs (also A)
__device__ __align__(16) uint32_t g_Xl[NPAD * 64];      // split input lo pairs
__device__ __align__(16) uint32_t g_Whi[2 * 8192];      // packed W hi, [m][n][kp]
__device__ __align__(16) uint32_t g_Wlo[2 * 8192];
__device__ __align__(16) int g_cntPos[NMAX];   // atomic counters; 0 on entry (K3 re-zeroes)
__device__ int   g_cnt[NMAX];                  // indeg
__device__ int   g_rowptr[NMAX];
__device__ int   g_rank[EMAX];                 // within-destination rank
__device__ int   g_eidx[EMAX];                 // CSR source indices
__device__ float g_dinv[NMAX];
__device__ __align__(16) float g_gate[D];
__device__ __align__(16) float g_hbias[D];

// ---------------------------------------------------------------- helpers
__device__ __forceinline__ void split2f(float a, float b, uint32_t& hi, uint32_t& lo) {
    asm("cvt.rn.bf16x2.f32 %0, %1, %2;" : "=r"(hi) : "f"(b), "f"(a));
    float ha = __uint_as_float(hi << 16);
    float hb = __uint_as_float(hi & 0xffff0000u);
    float la = a - ha;
    float lb = b - hb;
    asm("cvt.rn.bf16x2.f32 %0, %1, %2;" : "=r"(lo) : "f"(lb), "f"(la));
}
__device__ __forceinline__ float4 up4h(uint2 v) {
    float2 a = __half22float2(*(__half2*)&v.x);
    float2 b = __half22float2(*(__half2*)&v.y);
    return make_float4(a.x, a.y, b.x, b.y);
}

// ---------------------------------------------------------------- K1: const + split + count/rank
__global__ void k_pre(const float* __restrict__ W1, const float* __restrict__ W2,
                      const float* __restrict__ ctx, const float* __restrict__ Wg,
                      const float* __restrict__ bg,  const float* __restrict__ Wb,
                      const float* __restrict__ X,
                      const int* __restrict__ edst,
                      int n, int E, int nbS) {
    int blk = blockIdx.x;
    int tid = threadIdx.x;
    if (blk < 64) {                                     // W split/pack/transpose
        int idx = blk * 256 + tid;                      // 0..16383
        int m  = idx >> 13;
        int r  = idx & 8191;
        int nn = r & 127;
        int kp = r >> 7;
        const float* W = m ? W2 : W1;
        float w0 = W[(2 * kp) * D + nn];
        float w1 = W[(2 * kp + 1) * D + nn];
        uint32_t hi, lo;
        split2f(w0, w1, hi, lo);
        g_Whi[m * 8192 + nn * 64 + kp] = hi;
        g_Wlo[m * 8192 + nn * 64 + kp] = lo;
    } else if (blk < 80) {                              // hypernet
        int w    = (blk - 64) * 8 + (tid >> 5);
        int lane = tid & 31;
        float c0 = ctx[lane], c1 = ctx[lane + 32];
        float g = c0 * Wg[lane * D + w] + c1 * Wg[(lane + 32) * D + w];
        float b = c0 * Wb[lane * D + w] + c1 * Wb[(lane + 32) * D + w];
#pragma unroll
        for (int o = 16; o > 0; o >>= 1) {
            g += __shfl_down_sync(0xffffffffu, g, o);
            b += __shfl_down_sync(0xffffffffu, b, o);
        }
        if (lane == 0) {
            g_gate[w]  = 1.f / (1.f + __expf(-(g + bg[w])));
            g_hbias[w] = b;
        }
    } else if (blk < 80 + nbS) {                        // input split
        int i = (blk - 80) * 256 + tid;                 // float4 index
        if (i >= n * 32) return;
        float4 v = ((const float4*)X)[i];
        int row = i >> 5, c4 = i & 31;
        uint32_t h01, l01, h23, l23;
        split2f(v.x, v.y, h01, l01);
        split2f(v.z, v.w, h23, l23);
        *((uint2*)&g_Xh[(size_t)row * 64 + c4 * 2]) = make_uint2(h01, h23);
        *((uint2*)&g_Xl[(size_t)row * 64 + c4 * 2]) = make_uint2(l01, l23);
    } else {                                            // edge count + rank
        int i = (blk - 80 - nbS) * 256 + tid;
        if (i >= E) return;
        int d = edst[i];
        if ((unsigned)d < (unsigned)n)
            g_rank[i] = atomicAdd(&g_cntPos[d], 1);
    }
}

// ---------------------------------------------------------------- GEMM body (bf16x3 MMA, fp16 out)
__device__ __forceinline__ void mma16816(float* c, uint32_t a0, uint32_t a1,
                                         uint32_t a2, uint32_t a3,
                                         uint32_t b0, uint32_t b1) {
    asm volatile("mma.sync.aligned.m16n8k16.row.col.f32.bf16.bf16.f32 "
                 "{%0,%1,%2,%3}, {%4,%5,%6,%7}, {%8,%9}, {%0,%1,%2,%3};"
                 : "+f"(c[0]), "+f"(c[1]), "+f"(c[2]), "+f"(c[3])
                 : "r"(a0), "r"(a1), "r"(a2), "r"(a3), "r"(b0), "r"(b1));
}

// dmode 0: dinv computed inline from g_cntPos (conv1; safe while scan runs concurrently)
// dmode 1: dinv from g_dinv (conv2)
__device__ void gemm_body(uint32_t* sm, int r0, int wsel, int dmode, int n) {
    uint32_t* Xh = sm;
    uint32_t* Xl = Xh + 128 * PS;
    uint32_t* Wh = Xl + 128 * PS;
    uint32_t* Wl = Wh + 128 * PS;
    int tid = threadIdx.x;

    const uint32_t* gwh = g_Whi + wsel * 8192;
    const uint32_t* gwl = g_Wlo + wsel * 8192;
#pragma unroll
    for (int i = 0; i < 8; i++) {
        int q  = tid + i * 256;
        int wb = q * 4;
        int nn = wb >> 6, kp = wb & 63;
        *((uint4*)&Wh[nn * PS + kp]) = ((const uint4*)gwh)[q];
        *((uint4*)&Wl[nn * PS + kp]) = ((const uint4*)gwl)[q];
    }
    const uint4* gxh = (const uint4*)g_Xh + (size_t)r0 * 16;
    const uint4* gxl = (const uint4*)g_Xl + (size_t)r0 * 16;
#pragma unroll
    for (int i = 0; i < 8; i++) {
        int q   = tid + i * 256;
        int row = q >> 4, k4 = q & 15;
        *((uint4*)&Xh[row * PS + k4 * 4]) = gxh[q];
        *((uint4*)&Xl[row * PS + k4 * 4]) = gxl[q];
    }
    __syncthreads();

    int wid  = tid >> 5;
    int lane = tid & 31;
    int g    = lane >> 2;
    int tig  = lane & 3;
    int rA   = wid * 16 + g;

    float acc[16][4];
#pragma unroll
    for (int t = 0; t < 16; t++)
#pragma unroll
        for (int c = 0; c < 4; c++) acc[t][c] = 0.f;

#pragma unroll
    for (int s = 0; s < 8; s++) {
        int kp = s * 8;
        uint32_t ah0 = Xh[rA * PS + kp + tig];
        uint32_t ah1 = Xh[(rA + 8) * PS + kp + tig];
        uint32_t ah2 = Xh[rA * PS + kp + tig + 4];
        uint32_t ah3 = Xh[(rA + 8) * PS + kp + tig + 4];
        uint32_t al0 = Xl[rA * PS + kp + tig];
        uint32_t al1 = Xl[(rA + 8) * PS + kp + tig];
        uint32_t al2 = Xl[rA * PS + kp + tig + 4];
        uint32_t al3 = Xl[(rA + 8) * PS + kp + tig + 4];
#pragma unroll
        for (int nt = 0; nt < 16; nt++) {
            int nb = nt * 8 + g;
            uint32_t bh0 = Wh[nb * PS + kp + tig];
            uint32_t bh1 = Wh[nb * PS + kp + tig + 4];
            uint32_t bl0 = Wl[nb * PS + kp + tig];
            uint32_t bl1 = Wl[nb * PS + kp + tig + 4];
            mma16816(acc[nt], ah0, ah1, ah2, ah3, bh0, bh1);
            mma16816(acc[nt], ah0, ah1, ah2, ah3, bl0, bl1);
            mma16816(acc[nt], al0, al1, al2, al3, bh0, bh1);
        }
    }

    int gr0 = r0 + wid * 16 + g;
    int gr1 = gr0 + 8;
    float d0 = 0.f, d1 = 0.f;
    if (dmode == 0) {
        if (gr0 < n) d0 = rsqrtf((float)(g_cntPos[gr0] + 1));
        if (gr1 < n) d1 = rsqrtf((float)(g_cntPos[gr1] + 1));
    } else {
        if (gr0 < n) d0 = g_dinv[gr0];
        if (gr1 < n) d1 = g_dinv[gr1];
    }
#pragma unroll
    for (int nt = 0; nt < 16; nt++) {
        int c = nt * 8 + 2 * tig;
        if (gr0 < n)
            *((__half2*)&g_T16[(size_t)gr0 * D + c]) =
                __floats2half2_rn(acc[nt][0] * d0, acc[nt][1] * d0);
        if (gr1 < n)
            *((__half2*)&g_T16[(size_t)gr1 * D + c]) =
                __floats2half2_rn(acc[nt][2] * d1, acc[nt][3] * d1);
    }
}

// ---------------------------------------------------------------- K2: scan (block 0) || GEMM1 (inline dinv)
__global__ void __launch_bounds__(256)
k_scan_gemm(int n) {
    extern __shared__ uint32_t sm[];
    if (blockIdx.x != 0) {
        gemm_body(sm, (blockIdx.x - 1) * 128, 0, /*dmode=*/0, n);
        return;
    }
    // scan: rowptr/cnt/dinv from g_cntPos (READ-ONLY here; K3 zeroes)
    __shared__ int part[256];
    int tid = threadIdx.x;
    const int per = 196;                    // 256*196 >= 50000, %4==0
    int base = tid * per;
    int s = 0;
    for (int i = 0; i < per; i += 4) {
        int r = base + i;
        if (r + 3 < n) {
            int4 v = *((const int4*)&g_cntPos[r]);
            s += v.x + v.y + v.z + v.w;
        } else {
#pragma unroll
            for (int u = 0; u < 4; u++)
                if (r + u < n) s += g_cntPos[r + u];
        }
    }
    part[tid] = s;
    __syncthreads();
    for (int off = 1; off < 256; off <<= 1) {
        int v = (tid >= off) ? part[tid - off] : 0;
        __syncthreads();
        part[tid] += v;
        __syncthreads();
    }
    int run = (tid == 0) ? 0 : part[tid - 1];
    for (int i = 0; i < per; i += 4) {
        int r = base + i;
        if (r >= n) break;
        int4 v;
        if (r + 3 < n) v = *((const int4*)&g_cntPos[r]);
        else {
            v.x = (r     < n) ? g_cntPos[r]     : 0;
            v.y = (r + 1 < n) ? g_cntPos[r + 1] : 0;
            v.z = (r + 2 < n) ? g_cntPos[r + 2] : 0;
            v.w = (r + 3 < n) ? g_cntPos[r + 3] : 0;
        }
        int cv[4] = {v.x, v.y, v.z, v.w};
#pragma unroll
        for (int u = 0; u < 4; u++) {
            int rr = r + u;
            if (rr < n) {
                g_rowptr[rr] = run;
                g_cnt[rr]    = cv[u];
                run += cv[u];
                g_dinv[rr]   = rsqrtf((float)(cv[u] + 1));
            }
        }
    }
}

// ---------------------------------------------------------------- standalone GEMM (conv2)
__global__ void __launch_bounds__(256)
k_gemm(int wsel, int n) {
    extern __shared__ uint32_t sm[];
    gemm_body(sm, blockIdx.x * 128, wsel, /*dmode=*/1, n);
}

// ---------------------------------------------------------------- K3: CSR place || zero counters
__global__ void k_place_zero(const int* __restrict__ esrc,
                             const int* __restrict__ edst,
                             int E, int n, int nbE) {
    int blk = blockIdx.x;
    int tid = threadIdx.x;
    if (blk < nbE) {
        int i = blk * 256 + tid;
        if (i >= E) return;
        int s = esrc[i];
        int d = edst[i];
        if ((unsigned)s >= (unsigned)n || (unsigned)d >= (unsigned)n) return;
        g_eidx[g_rowptr[d] + g_rank[i]] = s;
    } else {
        int i = (blk - nbE) * 256 + tid;
        if (i < n) g_cntPos[i] = 0;         // restore invariant for next call
    }
}

// ---------------------------------------------------------------- fused gather + epilogue (fp16 T)
// T rows prescaled by dinv[src]: out[d] = epi( dinv[d] * sum_{s in d+in(d)} T[s] + b )
template <int MODE>
__global__ void __launch_bounds__(256, 6)
k_gather(float* __restrict__ Out, const float* __restrict__ bvec, int n) {
    int w = (blockIdx.x * blockDim.x + threadIdx.x) >> 5;
    if (w >= n) return;
    int lane = threadIdx.x & 31;
    int beg = g_rowptr[w];
    int cnt = g_cnt[w];
    const uint2* Tv = (const uint2*)g_T16;          // 32 uint2 per row

    float4 acc0 = up4h(Tv[(size_t)w * 32 + lane]);  // self term
    float4 acc1 = make_float4(0.f, 0.f, 0.f, 0.f);

    int j = 0;
    while (j < cnt) {
        int chunk = min(cnt - j, 32);
        int myidx = (lane < chunk) ? g_eidx[beg + j + lane] : 0;
        int t = 0;
        for (; t + 3 < chunk; t += 4) {
            int s0 = __shfl_sync(0xffffffffu, myidx, t);
            int s1 = __shfl_sync(0xffffffffu, myidx, t + 1);
            int s2 = __shfl_sync(0xffffffffu, myidx, t + 2);
            int s3 = __shfl_sync(0xffffffffu, myidx, t + 3);
            uint2 v0 = Tv[(size_t)s0 * 32 + lane];
            uint2 v1 = Tv[(size_t)s1 * 32 + lane];
            uint2 v2 = Tv[(size_t)s2 * 32 + lane];
            uint2 v3 = Tv[(size_t)s3 * 32 + lane];
            float4 f0 = up4h(v0);
            float4 f1 = up4h(v1);
            float4 f2 = up4h(v2);
            float4 f3 = up4h(v3);
            acc0.x += f0.x; acc0.y += f0.y; acc0.z += f0.z; acc0.w += f0.w;
            acc1.x += f1.x; acc1.y += f1.y; acc1.z += f1.z; acc1.w += f1.w;
            acc0.x += f2.x; acc0.y += f2.y; acc0.z += f2.z; acc0.w += f2.w;
            acc1.x += f3.x; acc1.y += f3.y; acc1.z += f3.z; acc1.w += f3.w;
        }
        for (; t < chunk; t++) {
            int s0 = __shfl_sync(0xffffffffu, myidx, t);
            float4 f0 = up4h(Tv[(size_t)s0 * 32 + lane]);
            acc0.x += f0.x; acc0.y += f0.y; acc0.z += f0.z; acc0.w += f0.w;
        }
        j += chunk;
    }
    acc0.x += acc1.x; acc0.y += acc1.y; acc0.z += acc1.z; acc0.w += acc1.w;

    float di = g_dinv[w];
    float4 b = ((const float4*)bvec)[lane];
    float4 o;
    o.x = acc0.x * di + b.x;
    o.y = acc0.y * di + b.y;
    o.z = acc0.z * di + b.z;
    o.w = acc0.w * di + b.w;
    if (MODE == 1) {
        o.x = o.x > 0.f ? o.x : 0.2f * o.x;
        o.y = o.y > 0.f ? o.y : 0.2f * o.y;
        o.z = o.z > 0.f ? o.z : 0.2f * o.z;
        o.w = o.w > 0.f ? o.w : 0.2f * o.w;
        uint32_t h01, l01, h23, l23;
        split2f(o.x, o.y, h01, l01);
        split2f(o.z, o.w, h23, l23);
        *((uint2*)&g_Xh[(size_t)w * 64 + lane * 2]) = make_uint2(h01, h23);
        *((uint2*)&g_Xl[(size_t)w * 64 + lane * 2]) = make_uint2(l01, l23);
    } else {
        float4 gt = ((const float4*)g_gate)[lane];
        float4 hb = ((const float4*)g_hbias)[lane];
        o.x = o.x * gt.x + hb.x;
        o.y = o.y * gt.y + hb.y;
        o.z = o.z * gt.z + hb.z;
        o.w = o.w * gt.w + hb.w;
        ((float4*)(Out + (size_t)w * D))[lane] = o;
    }
}

// ----------------------------------------------------------------
extern "C" void kernel_launch(void* const* d_in, const int* in_sizes, int n_in,
                              void* d_out, int out_size) {
    const float* x    = (const float*)d_in[0];
    const float* ctx  = (const float*)d_in[1];
    const float* W1   = (const float*)d_in[2];
    const float* b1   = (const float*)d_in[3];
    const float* W2   = (const float*)d_in[4];
    const float* b2   = (const float*)d_in[5];
    const float* Wg   = (const float*)d_in[6];
    const float* bg   = (const float*)d_in[7];
    const float* Wb   = (const float*)d_in[8];
    const int*   ei   = (const int*)d_in[9];     // int32 (JAX x64 disabled)
    float*       out  = (float*)d_out;

    int N = in_sizes[0] / D;
    int E = in_sizes[9] / 2;
    const int* esrc = ei;
    const int* edst = ei + E;

    int smemG = 4 * 128 * PS * sizeof(uint32_t);          // 139264 B
    cudaFuncSetAttribute(k_scan_gemm,
                         cudaFuncAttributeMaxDynamicSharedMemorySize, smemG);
    cudaFuncSetAttribute(k_gemm,
                         cudaFuncAttributeMaxDynamicSharedMemorySize, smemG);

    int nbS  = (N * 32 + 255) / 256;
    int nbE  = (E + 255) / 256;
    int nbN  = (N + 255) / 256;
    int gblk = (N + 127) / 128;
    long long gth = (long long)N * 32;
    int nbG  = (int)((gth + 255) / 256);

    // K1: const + input split + edge count/rank
    k_pre<<<80 + nbS + nbE, 256>>>(W1, W2, ctx, Wg, bg, Wb, x, edst, N, E, nbS);

    // K2: scan (block 0) || GEMM1 (fp16 out, inline dinv from counters)
    k_scan_gemm<<<1 + gblk, 256, smemG>>>(N);

    // K3: CSR place || zero counters
    k_place_zero<<<nbE + nbN, 256>>>(esrc, edst, E, N, nbE);

    // K4: conv1 gather -> A (split bf16)
    k_gather<1><<<nbG, 256>>>(nullptr, b1, N);

    // K5: GEMM2 (fp16 out, prescaled by g_dinv)
    k_gemm<<<gblk, 256, smemG>>>(1, N);

    // K6: conv2 gather -> out
    k_gather<2><<<nbG, 256>>>(out, b2, N);
}

// round 14
// speedup vs baseline: 2.0568x; 1.5546x over previous
#include <cuda_runtime.h>
#include <cuda_fp16.h>
#include <cuda_bf16.h>
#include <math.h>
#include <stdint.h>

#define D     128
#define NMAX  50000
#define EMAX  800000
#define NPAD  (NMAX + 128)
#define PS    68          // padded smem row stride (words)

// ---- scratch (device globals; zero at load) ----
__device__ __align__(16) __half   g_T16[NPAD * D];      // message table (fp16, prescaled)
__device__ __align__(16) uint32_t g_Xh[NPAD * 64];      // split input hi pairs (also A)
__device__ __align__(16) uint32_t g_Xl[NPAD * 64];      // split input lo pairs
__device__ __align__(16) uint32_t g_Whi[2 * 8192];      // packed W hi, [m][n][kp]
__device__ __align__(16) uint32_t g_Wlo[2 * 8192];
__device__ __align__(16) int g_cntPos[NMAX];   // atomic counters; 0 on entry (K3 re-zeroes)
__device__ __align__(16) int g_cnt[NMAX];      // indeg
__device__ __align__(16) int g_rowptr[NMAX];
__device__ int   g_rank[EMAX];                 // within-destination rank
__device__ int   g_eidx[EMAX];                 // CSR source indices
__device__ float g_dinv[NMAX];
__device__ __align__(16) float g_gate[D];
__device__ __align__(16) float g_hbias[D];

// ---------------------------------------------------------------- helpers
__device__ __forceinline__ void split2f(float a, float b, uint32_t& hi, uint32_t& lo) {
    asm("cvt.rn.bf16x2.f32 %0, %1, %2;" : "=r"(hi) : "f"(b), "f"(a));
    float ha = __uint_as_float(hi << 16);
    float hb = __uint_as_float(hi & 0xffff0000u);
    float la = a - ha;
    float lb = b - hb;
    asm("cvt.rn.bf16x2.f32 %0, %1, %2;" : "=r"(lo) : "f"(lb), "f"(la));
}
__device__ __forceinline__ float4 up4h(uint2 v) {
    float2 a = __half22float2(*(__half2*)&v.x);
    float2 b = __half22float2(*(__half2*)&v.y);
    return make_float4(a.x, a.y, b.x, b.y);
}

// ---------------------------------------------------------------- K1: const + split + count/rank
__global__ void k_pre(const float* __restrict__ W1, const float* __restrict__ W2,
                      const float* __restrict__ ctx, const float* __restrict__ Wg,
                      const float* __restrict__ bg,  const float* __restrict__ Wb,
                      const float* __restrict__ X,
                      const int* __restrict__ edst,
                      int n, int E, int nbS) {
    int blk = blockIdx.x;
    int tid = threadIdx.x;
    if (blk < 64) {                                     // W split/pack/transpose
        int idx = blk * 256 + tid;                      // 0..16383
        int m  = idx >> 13;
        int r  = idx & 8191;
        int nn = r & 127;
        int kp = r >> 7;
        const float* W = m ? W2 : W1;
        float w0 = W[(2 * kp) * D + nn];
        float w1 = W[(2 * kp + 1) * D + nn];
        uint32_t hi, lo;
        split2f(w0, w1, hi, lo);
        g_Whi[m * 8192 + nn * 64 + kp] = hi;
        g_Wlo[m * 8192 + nn * 64 + kp] = lo;
    } else if (blk < 80) {                              // hypernet
        int w    = (blk - 64) * 8 + (tid >> 5);
        int lane = tid & 31;
        float c0 = ctx[lane], c1 = ctx[lane + 32];
        float g = c0 * Wg[lane * D + w] + c1 * Wg[(lane + 32) * D + w];
        float b = c0 * Wb[lane * D + w] + c1 * Wb[(lane + 32) * D + w];
#pragma unroll
        for (int o = 16; o > 0; o >>= 1) {
            g += __shfl_down_sync(0xffffffffu, g, o);
            b += __shfl_down_sync(0xffffffffu, b, o);
        }
        if (lane == 0) {
            g_gate[w]  = 1.f / (1.f + __expf(-(g + bg[w])));
            g_hbias[w] = b;
        }
    } else if (blk < 80 + nbS) {                        // input split
        int i = (blk - 80) * 256 + tid;                 // float4 index
        if (i >= n * 32) return;
        float4 v = ((const float4*)X)[i];
        int row = i >> 5, c4 = i & 31;
        uint32_t h01, l01, h23, l23;
        split2f(v.x, v.y, h01, l01);
        split2f(v.z, v.w, h23, l23);
        *((uint2*)&g_Xh[(size_t)row * 64 + c4 * 2]) = make_uint2(h01, h23);
        *((uint2*)&g_Xl[(size_t)row * 64 + c4 * 2]) = make_uint2(l01, l23);
    } else {                                            // edge count + rank
        int i = (blk - 80 - nbS) * 256 + tid;
        if (i >= E) return;
        int d = edst[i];
        if ((unsigned)d < (unsigned)n)
            g_rank[i] = atomicAdd(&g_cntPos[d], 1);
    }
}

// ---------------------------------------------------------------- GEMM body (bf16x3 MMA, fp16 out)
__device__ __forceinline__ void mma16816(float* c, uint32_t a0, uint32_t a1,
                                         uint32_t a2, uint32_t a3,
                                         uint32_t b0, uint32_t b1) {
    asm volatile("mma.sync.aligned.m16n8k16.row.col.f32.bf16.bf16.f32 "
                 "{%0,%1,%2,%3}, {%4,%5,%6,%7}, {%8,%9}, {%0,%1,%2,%3};"
                 : "+f"(c[0]), "+f"(c[1]), "+f"(c[2]), "+f"(c[3])
                 : "r"(a0), "r"(a1), "r"(a2), "r"(a3), "r"(b0), "r"(b1));
}

// dmode 0: dinv computed inline from g_cntPos (conv1; counters read-only during K2)
// dmode 1: dinv from g_dinv (conv2)
__device__ void gemm_body(uint32_t* sm, int r0, int wsel, int dmode, int n) {
    uint32_t* Xh = sm;
    uint32_t* Xl = Xh + 128 * PS;
    uint32_t* Wh = Xl + 128 * PS;
    uint32_t* Wl = Wh + 128 * PS;
    int tid = threadIdx.x;

    const uint32_t* gwh = g_Whi + wsel * 8192;
    const uint32_t* gwl = g_Wlo + wsel * 8192;
#pragma unroll
    for (int i = 0; i < 8; i++) {
        int q  = tid + i * 256;
        int wb = q * 4;
        int nn = wb >> 6, kp = wb & 63;
        *((uint4*)&Wh[nn * PS + kp]) = ((const uint4*)gwh)[q];
        *((uint4*)&Wl[nn * PS + kp]) = ((const uint4*)gwl)[q];
    }
    const uint4* gxh = (const uint4*)g_Xh + (size_t)r0 * 16;
    const uint4* gxl = (const uint4*)g_Xl + (size_t)r0 * 16;
#pragma unroll
    for (int i = 0; i < 8; i++) {
        int q   = tid + i * 256;
        int row = q >> 4, k4 = q & 15;
        *((uint4*)&Xh[row * PS + k4 * 4]) = gxh[q];
        *((uint4*)&Xl[row * PS + k4 * 4]) = gxl[q];
    }
    __syncthreads();

    int wid  = tid >> 5;
    int lane = tid & 31;
    int g    = lane >> 2;
    int tig  = lane & 3;
    int rA   = wid * 16 + g;

    float acc[16][4];
#pragma unroll
    for (int t = 0; t < 16; t++)
#pragma unroll
        for (int c = 0; c < 4; c++) acc[t][c] = 0.f;

#pragma unroll
    for (int s = 0; s < 8; s++) {
        int kp = s * 8;
        uint32_t ah0 = Xh[rA * PS + kp + tig];
        uint32_t ah1 = Xh[(rA + 8) * PS + kp + tig];
        uint32_t ah2 = Xh[rA * PS + kp + tig + 4];
        uint32_t ah3 = Xh[(rA + 8) * PS + kp + tig + 4];
        uint32_t al0 = Xl[rA * PS + kp + tig];
        uint32_t al1 = Xl[(rA + 8) * PS + kp + tig];
        uint32_t al2 = Xl[rA * PS + kp + tig + 4];
        uint32_t al3 = Xl[(rA + 8) * PS + kp + tig + 4];
#pragma unroll
        for (int nt = 0; nt < 16; nt++) {
            int nb = nt * 8 + g;
            uint32_t bh0 = Wh[nb * PS + kp + tig];
            uint32_t bh1 = Wh[nb * PS + kp + tig + 4];
            uint32_t bl0 = Wl[nb * PS + kp + tig];
            uint32_t bl1 = Wl[nb * PS + kp + tig + 4];
            mma16816(acc[nt], ah0, ah1, ah2, ah3, bh0, bh1);
            mma16816(acc[nt], ah0, ah1, ah2, ah3, bl0, bl1);
            mma16816(acc[nt], al0, al1, al2, al3, bh0, bh1);
        }
    }

    int gr0 = r0 + wid * 16 + g;
    int gr1 = gr0 + 8;
    float d0 = 0.f, d1 = 0.f;
    if (dmode == 0) {
        if (gr0 < n) d0 = rsqrtf((float)(g_cntPos[gr0] + 1));
        if (gr1 < n) d1 = rsqrtf((float)(g_cntPos[gr1] + 1));
    } else {
        if (gr0 < n) d0 = g_dinv[gr0];
        if (gr1 < n) d1 = g_dinv[gr1];
    }
#pragma unroll
    for (int nt = 0; nt < 16; nt++) {
        int c = nt * 8 + 2 * tig;
        if (gr0 < n)
            *((__half2*)&g_T16[(size_t)gr0 * D + c]) =
                __floats2half2_rn(acc[nt][0] * d0, acc[nt][1] * d0);
        if (gr1 < n)
            *((__half2*)&g_T16[(size_t)gr1 * D + c]) =
                __floats2half2_rn(acc[nt][2] * d1, acc[nt][3] * d1);
    }
}

// ---------------------------------------------------------------- K2: rowptr-only scan (block 0) || GEMM1
__global__ void __launch_bounds__(256)
k_scan_gemm(int n) {
    extern __shared__ uint32_t sm[];
    if (blockIdx.x != 0) {
        gemm_body(sm, (blockIdx.x - 1) * 128, 0, /*dmode=*/0, n);
        return;
    }
    // prefix-sum of g_cntPos -> g_rowptr (int4 in, int4 out); NOTHING else.
    __shared__ int part[256];
    int tid = threadIdx.x;
    const int per = 196;                    // 256*196 >= 50000, %4==0
    int base = tid * per;
    int s = 0;
    for (int i = 0; i < per; i += 4) {
        int r = base + i;
        if (r + 3 < n) {
            int4 v = *((const int4*)&g_cntPos[r]);
            s += v.x + v.y + v.z + v.w;
        } else {
#pragma unroll
            for (int u = 0; u < 4; u++)
                if (r + u < n) s += g_cntPos[r + u];
        }
    }
    part[tid] = s;
    __syncthreads();
    for (int off = 1; off < 256; off <<= 1) {
        int v = (tid >= off) ? part[tid - off] : 0;
        __syncthreads();
        part[tid] += v;
        __syncthreads();
    }
    int run = (tid == 0) ? 0 : part[tid - 1];
    for (int i = 0; i < per; i += 4) {
        int r = base + i;
        if (r >= n) break;
        if (r + 3 < n) {
            int4 v = *((const int4*)&g_cntPos[r]);
            int4 rp;
            rp.x = run;
            rp.y = rp.x + v.x;
            rp.z = rp.y + v.y;
            rp.w = rp.z + v.z;
            run  = rp.w + v.w;
            *((int4*)&g_rowptr[r]) = rp;
        } else {
#pragma unroll
            for (int u = 0; u < 4; u++) {
                int rr = r + u;
                if (rr < n) {
                    g_rowptr[rr] = run;
                    run += g_cntPos[rr];
                }
            }
        }
    }
}

// ---------------------------------------------------------------- standalone GEMM (conv2)
__global__ void __launch_bounds__(256)
k_gemm(int wsel, int n) {
    extern __shared__ uint32_t sm[];
    gemm_body(sm, blockIdx.x * 128, wsel, /*dmode=*/1, n);
}

// ---------------------------------------------------------------- K3: CSR place || node finalize
// node finalize: cnt/dinv from counters, then zero counters (parallel over N)
__global__ void k_place_fin(const int* __restrict__ esrc,
                            const int* __restrict__ edst,
                            int E, int n, int nbE) {
    int blk = blockIdx.x;
    int tid = threadIdx.x;
    if (blk < nbE) {
        int i = blk * 256 + tid;
        if (i >= E) return;
        int s = esrc[i];
        int d = edst[i];
        if ((unsigned)s >= (unsigned)n || (unsigned)d >= (unsigned)n) return;
        g_eidx[g_rowptr[d] + g_rank[i]] = s;
    } else {
        int i = (blk - nbE) * 256 + tid;
        if (i < n) {
            int c = g_cntPos[i];
            g_cnt[i]  = c;
            g_dinv[i] = rsqrtf((float)(c + 1));
            g_cntPos[i] = 0;                // restore invariant for next call
        }
    }
}

// ---------------------------------------------------------------- fused gather + epilogue (fp16 T)
// T rows prescaled by dinv[src]: out[d] = epi( dinv[d] * sum_{s in d+in(d)} T[s] + b )
template <int MODE>
__global__ void __launch_bounds__(256, 6)
k_gather(float* __restrict__ Out, const float* __restrict__ bvec, int n) {
    int w = (blockIdx.x * blockDim.x + threadIdx.x) >> 5;
    if (w >= n) return;
    int lane = threadIdx.x & 31;
    int beg = g_rowptr[w];
    int cnt = g_cnt[w];
    const uint2* Tv = (const uint2*)g_T16;          // 32 uint2 per row

    float4 acc0 = up4h(Tv[(size_t)w * 32 + lane]);  // self term
    float4 acc1 = make_float4(0.f, 0.f, 0.f, 0.f);

    int j = 0;
    while (j < cnt) {
        int chunk = min(cnt - j, 32);
        int myidx = (lane < chunk) ? g_eidx[beg + j + lane] : 0;
        int t = 0;
        for (; t + 3 < chunk; t += 4) {
            int s0 = __shfl_sync(0xffffffffu, myidx, t);
            int s1 = __shfl_sync(0xffffffffu, myidx, t + 1);
            int s2 = __shfl_sync(0xffffffffu, myidx, t + 2);
            int s3 = __shfl_sync(0xffffffffu, myidx, t + 3);
            uint2 v0 = Tv[(size_t)s0 * 32 + lane];
            uint2 v1 = Tv[(size_t)s1 * 32 + lane];
            uint2 v2 = Tv[(size_t)s2 * 32 + lane];
            uint2 v3 = Tv[(size_t)s3 * 32 + lane];
            float4 f0 = up4h(v0);
            float4 f1 = up4h(v1);
            float4 f2 = up4h(v2);
            float4 f3 = up4h(v3);
            acc0.x += f0.x; acc0.y += f0.y; acc0.z += f0.z; acc0.w += f0.w;
            acc1.x += f1.x; acc1.y += f1.y; acc1.z += f1.z; acc1.w += f1.w;
            acc0.x += f2.x; acc0.y += f2.y; acc0.z += f2.z; acc0.w += f2.w;
            acc1.x += f3.x; acc1.y += f3.y; acc1.z += f3.z; acc1.w += f3.w;
        }
        for (; t < chunk; t++) {
            int s0 = __shfl_sync(0xffffffffu, myidx, t);
            float4 f0 = up4h(Tv[(size_t)s0 * 32 + lane]);
            acc0.x += f0.x; acc0.y += f0.y; acc0.z += f0.z; acc0.w += f0.w;
        }
        j += chunk;
    }
    acc0.x += acc1.x; acc0.y += acc1.y; acc0.z += acc1.z; acc0.w += acc1.w;

    float di = g_dinv[w];
    float4 b = ((const float4*)bvec)[lane];
    float4 o;
    o.x = acc0.x * di + b.x;
    o.y = acc0.y * di + b.y;
    o.z = acc0.z * di + b.z;
    o.w = acc0.w * di + b.w;
    if (MODE == 1) {
        o.x = o.x > 0.f ? o.x : 0.2f * o.x;
        o.y = o.y > 0.f ? o.y : 0.2f * o.y;
        o.z = o.z > 0.f ? o.z : 0.2f * o.z;
        o.w = o.w > 0.f ? o.w : 0.2f * o.w;
        uint32_t h01, l01, h23, l23;
        split2f(o.x, o.y, h01, l01);
        split2f(o.z, o.w, h23, l23);
        *((uint2*)&g_Xh[(size_t)w * 64 + lane * 2]) = make_uint2(h01, h23);
        *((uint2*)&g_Xl[(size_t)w * 64 + lane * 2]) = make_uint2(l01, l23);
    } else {
        float4 gt = ((const float4*)g_gate)[lane];
        float4 hb = ((const float4*)g_hbias)[lane];
        o.x = o.x * gt.x + hb.x;
        o.y = o.y * gt.y + hb.y;
        o.z = o.z * gt.z + hb.z;
        o.w = o.w * gt.w + hb.w;
        ((float4*)(Out + (size_t)w * D))[lane] = o;
    }
}

// ----------------------------------------------------------------
extern "C" void kernel_launch(void* const* d_in, const int* in_sizes, int n_in,
                              void* d_out, int out_size) {
    const float* x    = (const float*)d_in[0];
    const float* ctx  = (const float*)d_in[1];
    const float* W1   = (const float*)d_in[2];
    const float* b1   = (const float*)d_in[3];
    const float* W2   = (const float*)d_in[4];
    const float* b2   = (const float*)d_in[5];
    const float* Wg   = (const float*)d_in[6];
    const float* bg   = (const float*)d_in[7];
    const float* Wb   = (const float*)d_in[8];
    const int*   ei   = (const int*)d_in[9];     // int32 (JAX x64 disabled)
    float*       out  = (float*)d_out;

    int N = in_sizes[0] / D;
    int E = in_sizes[9] / 2;
    const int* esrc = ei;
    const int* edst = ei + E;

    int smemG = 4 * 128 * PS * sizeof(uint32_t);          // 139264 B
    cudaFuncSetAttribute(k_scan_gemm,
                         cudaFuncAttributeMaxDynamicSharedMemorySize, smemG);
    cudaFuncSetAttribute(k_gemm,
                         cudaFuncAttributeMaxDynamicSharedMemorySize, smemG);

    int nbS  = (N * 32 + 255) / 256;
    int nbE  = (E + 255) / 256;
    int nbN  = (N + 255) / 256;
    int gblk = (N + 127) / 128;
    long long gth = (long long)N * 32;
    int nbG  = (int)((gth + 255) / 256);

    // K1: const + input split + edge count/rank
    k_pre<<<80 + nbS + nbE, 256>>>(W1, W2, ctx, Wg, bg, Wb, x, edst, N, E, nbS);

    // K2: rowptr scan (block 0, prefix-sum only) || GEMM1
    k_scan_gemm<<<1 + gblk, 256, smemG>>>(N);

    // K3: CSR place || node finalize (cnt/dinv/zero)
    k_place_fin<<<nbE + nbN, 256>>>(esrc, edst, E, N, nbE);

    // K4: conv1 gather -> A (split bf16)
    k_gather<1><<<nbG, 256>>>(nullptr, b1, N);

    // K5: GEMM2 (fp16 out, prescaled by g_dinv)
    k_gemm<<<gblk, 256, smemG>>>(1, N);

    // K6: conv2 gather -> out
    k_gather<2><<<nbG, 256>>>(out, b2, N);
}

// round 15
// speedup vs baseline: 2.1136x; 1.0276x over previous
#include <cuda_runtime.h>
#include <cuda_fp16.h>
#include <cuda_bf16.h>
#include <math.h>
#include <stdint.h>

#define D     128
#define NMAX  50000
#define EMAX  800000
#define NPAD  (NMAX + 128)
#define PS    68          // padded smem row stride (words)

// ---- scratch (device globals; zero at load) ----
__device__ __align__(16) __half   g_T16[NPAD * D];      // message table (fp16, prescaled)
__device__ __align__(16) uint32_t g_Xh[NPAD * 64];      // split input hi pairs (also A)
__device__ __align__(16) uint32_t g_Xl[NPAD * 64];      // split input lo pairs
__device__ __align__(16) uint32_t g_Whi[2 * 8192];      // packed W hi, [m][n][kp]
__device__ __align__(16) uint32_t g_Wlo[2 * 8192];
__device__ __align__(16) int g_cntPos[NMAX];   // atomic counters; 0 on entry (K3 re-zeroes)
__device__ __align__(16) int g_cnt[NMAX];      // indeg
__device__ __align__(16) int g_rowptr[NMAX];
__device__ int   g_rank[EMAX];                 // within-destination rank
__device__ int   g_eidx[EMAX];                 // CSR source indices
__device__ float g_dinv[NMAX];
__device__ __align__(16) float g_gate[D];
__device__ __align__(16) float g_hbias[D];

// ---------------------------------------------------------------- helpers
__device__ __forceinline__ void split2f(float a, float b, uint32_t& hi, uint32_t& lo) {
    asm("cvt.rn.bf16x2.f32 %0, %1, %2;" : "=r"(hi) : "f"(b), "f"(a));
    float ha = __uint_as_float(hi << 16);
    float hb = __uint_as_float(hi & 0xffff0000u);
    float la = a - ha;
    float lb = b - hb;
    asm("cvt.rn.bf16x2.f32 %0, %1, %2;" : "=r"(lo) : "f"(lb), "f"(la));
}
__device__ __forceinline__ float4 up4h(uint2 v) {
    float2 a = __half22float2(*(__half2*)&v.x);
    float2 b = __half22float2(*(__half2*)&v.y);
    return make_float4(a.x, a.y, b.x, b.y);
}
__device__ __forceinline__ __half2 h2(uint32_t u) { return *(__half2*)&u; }

// ---------------------------------------------------------------- K1: const + split + count/rank
__global__ void k_pre(const float* __restrict__ W1, const float* __restrict__ W2,
                      const float* __restrict__ ctx, const float* __restrict__ Wg,
                      const float* __restrict__ bg,  const float* __restrict__ Wb,
                      const float* __restrict__ X,
                      const int* __restrict__ edst,
                      int n, int E, int nbS) {
    int blk = blockIdx.x;
    int tid = threadIdx.x;
    if (blk < 64) {                                     // W split/pack/transpose
        int idx = blk * 256 + tid;                      // 0..16383
        int m  = idx >> 13;
        int r  = idx & 8191;
        int nn = r & 127;
        int kp = r >> 7;
        const float* W = m ? W2 : W1;
        float w0 = W[(2 * kp) * D + nn];
        float w1 = W[(2 * kp + 1) * D + nn];
        uint32_t hi, lo;
        split2f(w0, w1, hi, lo);
        g_Whi[m * 8192 + nn * 64 + kp] = hi;
        g_Wlo[m * 8192 + nn * 64 + kp] = lo;
    } else if (blk < 80) {                              // hypernet
        int w    = (blk - 64) * 8 + (tid >> 5);
        int lane = tid & 31;
        float c0 = ctx[lane], c1 = ctx[lane + 32];
        float g = c0 * Wg[lane * D + w] + c1 * Wg[(lane + 32) * D + w];
        float b = c0 * Wb[lane * D + w] + c1 * Wb[(lane + 32) * D + w];
#pragma unroll
        for (int o = 16; o > 0; o >>= 1) {
            g += __shfl_down_sync(0xffffffffu, g, o);
            b += __shfl_down_sync(0xffffffffu, b, o);
        }
        if (lane == 0) {
            g_gate[w]  = 1.f / (1.f + __expf(-(g + bg[w])));
            g_hbias[w] = b;
        }
    } else if (blk < 80 + nbS) {                        // input split
        int i = (blk - 80) * 256 + tid;                 // float4 index
        if (i >= n * 32) return;
        float4 v = ((const float4*)X)[i];
        int row = i >> 5, c4 = i & 31;
        uint32_t h01, l01, h23, l23;
        split2f(v.x, v.y, h01, l01);
        split2f(v.z, v.w, h23, l23);
        *((uint2*)&g_Xh[(size_t)row * 64 + c4 * 2]) = make_uint2(h01, h23);
        *((uint2*)&g_Xl[(size_t)row * 64 + c4 * 2]) = make_uint2(l01, l23);
    } else {                                            // edge count + rank
        int i = (blk - 80 - nbS) * 256 + tid;
        if (i >= E) return;
        int d = edst[i];
        if ((unsigned)d < (unsigned)n)
            g_rank[i] = atomicAdd(&g_cntPos[d], 1);
    }
}

// ---------------------------------------------------------------- GEMM body (bf16x3 MMA, fp16 out)
__device__ __forceinline__ void mma16816(float* c, uint32_t a0, uint32_t a1,
                                         uint32_t a2, uint32_t a3,
                                         uint32_t b0, uint32_t b1) {
    asm volatile("mma.sync.aligned.m16n8k16.row.col.f32.bf16.bf16.f32 "
                 "{%0,%1,%2,%3}, {%4,%5,%6,%7}, {%8,%9}, {%0,%1,%2,%3};"
                 : "+f"(c[0]), "+f"(c[1]), "+f"(c[2]), "+f"(c[3])
                 : "r"(a0), "r"(a1), "r"(a2), "r"(a3), "r"(b0), "r"(b1));
}

// dmode 0: dinv computed inline from g_cntPos (conv1; counters read-only during K2)
// dmode 1: dinv from g_dinv (conv2)
__device__ void gemm_body(uint32_t* sm, int r0, int wsel, int dmode, int n) {
    uint32_t* Xh = sm;
    uint32_t* Xl = Xh + 128 * PS;
    uint32_t* Wh = Xl + 128 * PS;
    uint32_t* Wl = Wh + 128 * PS;
    int tid = threadIdx.x;

    const uint32_t* gwh = g_Whi + wsel * 8192;
    const uint32_t* gwl = g_Wlo + wsel * 8192;
#pragma unroll
    for (int i = 0; i < 8; i++) {
        int q  = tid + i * 256;
        int wb = q * 4;
        int nn = wb >> 6, kp = wb & 63;
        *((uint4*)&Wh[nn * PS + kp]) = ((const uint4*)gwh)[q];
        *((uint4*)&Wl[nn * PS + kp]) = ((const uint4*)gwl)[q];
    }
    const uint4* gxh = (const uint4*)g_Xh + (size_t)r0 * 16;
    const uint4* gxl = (const uint4*)g_Xl + (size_t)r0 * 16;
#pragma unroll
    for (int i = 0; i < 8; i++) {
        int q   = tid + i * 256;
        int row = q >> 4, k4 = q & 15;
        *((uint4*)&Xh[row * PS + k4 * 4]) = gxh[q];
        *((uint4*)&Xl[row * PS + k4 * 4]) = gxl[q];
    }
    __syncthreads();

    int wid  = tid >> 5;
    int lane = tid & 31;
    int g    = lane >> 2;
    int tig  = lane & 3;
    int rA   = wid * 16 + g;

    float acc[16][4];
#pragma unroll
    for (int t = 0; t < 16; t++)
#pragma unroll
        for (int c = 0; c < 4; c++) acc[t][c] = 0.f;

#pragma unroll
    for (int s = 0; s < 8; s++) {
        int kp = s * 8;
        uint32_t ah0 = Xh[rA * PS + kp + tig];
        uint32_t ah1 = Xh[(rA + 8) * PS + kp + tig];
        uint32_t ah2 = Xh[rA * PS + kp + tig + 4];
        uint32_t ah3 = Xh[(rA + 8) * PS + kp + tig + 4];
        uint32_t al0 = Xl[rA * PS + kp + tig];
        uint32_t al1 = Xl[(rA + 8) * PS + kp + tig];
        uint32_t al2 = Xl[rA * PS + kp + tig + 4];
        uint32_t al3 = Xl[(rA + 8) * PS + kp + tig + 4];
#pragma unroll
        for (int nt = 0; nt < 16; nt++) {
            int nb = nt * 8 + g;
            uint32_t bh0 = Wh[nb * PS + kp + tig];
            uint32_t bh1 = Wh[nb * PS + kp + tig + 4];
            uint32_t bl0 = Wl[nb * PS + kp + tig];
            uint32_t bl1 = Wl[nb * PS + kp + tig + 4];
            mma16816(acc[nt], ah0, ah1, ah2, ah3, bh0, bh1);
            mma16816(acc[nt], ah0, ah1, ah2, ah3, bl0, bl1);
            mma16816(acc[nt], al0, al1, al2, al3, bh0, bh1);
        }
    }

    int gr0 = r0 + wid * 16 + g;
    int gr1 = gr0 + 8;
    float d0 = 0.f, d1 = 0.f;
    if (dmode == 0) {
        if (gr0 < n) d0 = rsqrtf((float)(g_cntPos[gr0] + 1));
        if (gr1 < n) d1 = rsqrtf((float)(g_cntPos[gr1] + 1));
    } else {
        if (gr0 < n) d0 = g_dinv[gr0];
        if (gr1 < n) d1 = g_dinv[gr1];
    }
#pragma unroll
    for (int nt = 0; nt < 16; nt++) {
        int c = nt * 8 + 2 * tig;
        if (gr0 < n)
            *((__half2*)&g_T16[(size_t)gr0 * D + c]) =
                __floats2half2_rn(acc[nt][0] * d0, acc[nt][1] * d0);
        if (gr1 < n)
            *((__half2*)&g_T16[(size_t)gr1 * D + c]) =
                __floats2half2_rn(acc[nt][2] * d1, acc[nt][3] * d1);
    }
}

// ---------------------------------------------------------------- K2: rowptr-only scan (block 0) || GEMM1
__global__ void __launch_bounds__(256)
k_scan_gemm(int n) {
    extern __shared__ uint32_t sm[];
    if (blockIdx.x != 0) {
        gemm_body(sm, (blockIdx.x - 1) * 128, 0, /*dmode=*/0, n);
        return;
    }
    // prefix-sum of g_cntPos -> g_rowptr (int4 in, int4 out); NOTHING else.
    __shared__ int part[256];
    int tid = threadIdx.x;
    const int per = 196;                    // 256*196 >= 50000, %4==0
    int base = tid * per;
    int s = 0;
    for (int i = 0; i < per; i += 4) {
        int r = base + i;
        if (r + 3 < n) {
            int4 v = *((const int4*)&g_cntPos[r]);
            s += v.x + v.y + v.z + v.w;
        } else {
#pragma unroll
            for (int u = 0; u < 4; u++)
                if (r + u < n) s += g_cntPos[r + u];
        }
    }
    part[tid] = s;
    __syncthreads();
    for (int off = 1; off < 256; off <<= 1) {
        int v = (tid >= off) ? part[tid - off] : 0;
        __syncthreads();
        part[tid] += v;
        __syncthreads();
    }
    int run = (tid == 0) ? 0 : part[tid - 1];
    for (int i = 0; i < per; i += 4) {
        int r = base + i;
        if (r >= n) break;
        if (r + 3 < n) {
            int4 v = *((const int4*)&g_cntPos[r]);
            int4 rp;
            rp.x = run;
            rp.y = rp.x + v.x;
            rp.z = rp.y + v.y;
            rp.w = rp.z + v.z;
            run  = rp.w + v.w;
            *((int4*)&g_rowptr[r]) = rp;
        } else {
#pragma unroll
            for (int u = 0; u < 4; u++) {
                int rr = r + u;
                if (rr < n) {
                    g_rowptr[rr] = run;
                    run += g_cntPos[rr];
                }
            }
        }
    }
}

// ---------------------------------------------------------------- standalone GEMM (conv2)
__global__ void __launch_bounds__(256)
k_gemm(int wsel, int n) {
    extern __shared__ uint32_t sm[];
    gemm_body(sm, blockIdx.x * 128, wsel, /*dmode=*/1, n);
}

// ---------------------------------------------------------------- K3: CSR place || node finalize
__global__ void k_place_fin(const int* __restrict__ esrc,
                            const int* __restrict__ edst,
                            int E, int n, int nbE) {
    int blk = blockIdx.x;
    int tid = threadIdx.x;
    if (blk < nbE) {
        int i = blk * 256 + tid;
        if (i >= E) return;
        int s = esrc[i];
        int d = edst[i];
        if ((unsigned)s >= (unsigned)n || (unsigned)d >= (unsigned)n) return;
        g_eidx[g_rowptr[d] + g_rank[i]] = s;
    } else {
        int i = (blk - nbE) * 256 + tid;
        if (i < n) {
            int c = g_cntPos[i];
            g_cnt[i]  = c;
            g_dinv[i] = rsqrtf((float)(c + 1));
            g_cntPos[i] = 0;                // restore invariant for next call
        }
    }
}

// ---------------------------------------------------------------- fused gather + epilogue (fp16 T)
// T rows prescaled by dinv[src]: out[d] = epi( dinv[d] * sum_{s in d+in(d)} T[s] + b )
// 4 edges/iter summed in fp16 (pairwise HADD2 tree), flushed to fp32 per group.
template <int MODE>
__global__ void __launch_bounds__(256, 6)
k_gather(float* __restrict__ Out, const float* __restrict__ bvec, int n) {
    int w = (blockIdx.x * blockDim.x + threadIdx.x) >> 5;
    if (w >= n) return;
    int lane = threadIdx.x & 31;
    int beg = g_rowptr[w];
    int cnt = g_cnt[w];
    const char* base = (const char*)g_T16 + lane * 8;   // per-lane column base

    float4 acc = up4h(*(const uint2*)(base + ((unsigned)w << 8)));   // self term

    int j = 0;
    while (j < cnt) {
        int chunk = min(cnt - j, 32);
        unsigned myoff = 0;
        if (lane < chunk) myoff = (unsigned)g_eidx[beg + j + lane] << 8;
        int t = 0;
        for (; t + 3 < chunk; t += 4) {
            unsigned o0 = __shfl_sync(0xffffffffu, myoff, t);
            unsigned o1 = __shfl_sync(0xffffffffu, myoff, t + 1);
            unsigned o2 = __shfl_sync(0xffffffffu, myoff, t + 2);
            unsigned o3 = __shfl_sync(0xffffffffu, myoff, t + 3);
            uint2 v0 = *(const uint2*)(base + o0);
            uint2 v1 = *(const uint2*)(base + o1);
            uint2 v2 = *(const uint2*)(base + o2);
            uint2 v3 = *(const uint2*)(base + o3);
            __half2 p0 = __hadd2(h2(v0.x), h2(v1.x));
            __half2 p1 = __hadd2(h2(v2.x), h2(v3.x));
            __half2 q0 = __hadd2(h2(v0.y), h2(v1.y));
            __half2 q1 = __hadd2(h2(v2.y), h2(v3.y));
            float2 f0 = __half22float2(__hadd2(p0, p1));
            float2 f1 = __half22float2(__hadd2(q0, q1));
            acc.x += f0.x; acc.y += f0.y; acc.z += f1.x; acc.w += f1.y;
        }
        for (; t < chunk; t++) {
            unsigned o = __shfl_sync(0xffffffffu, myoff, t);
            float4 f = up4h(*(const uint2*)(base + o));
            acc.x += f.x; acc.y += f.y; acc.z += f.z; acc.w += f.w;
        }
        j += chunk;
    }

    float di = g_dinv[w];
    float4 b = ((const float4*)bvec)[lane];
    float4 o;
    o.x = acc.x * di + b.x;
    o.y = acc.y * di + b.y;
    o.z = acc.z * di + b.z;
    o.w = acc.w * di + b.w;
    if (MODE == 1) {
        o.x = o.x > 0.f ? o.x : 0.2f * o.x;
        o.y = o.y > 0.f ? o.y : 0.2f * o.y;
        o.z = o.z > 0.f ? o.z : 0.2f * o.z;
        o.w = o.w > 0.f ? o.w : 0.2f * o.w;
        uint32_t h01, l01, h23, l23;
        split2f(o.x, o.y, h01, l01);
        split2f(o.z, o.w, h23, l23);
        *((uint2*)&g_Xh[(size_t)w * 64 + lane * 2]) = make_uint2(h01, h23);
        *((uint2*)&g_Xl[(size_t)w * 64 + lane * 2]) = make_uint2(l01, l23);
    } else {
        float4 gt = ((const float4*)g_gate)[lane];
        float4 hb = ((const float4*)g_hbias)[lane];
        o.x = o.x * gt.x + hb.x;
        o.y = o.y * gt.y + hb.y;
        o.z = o.z * gt.z + hb.z;
        o.w = o.w * gt.w + hb.w;
        ((float4*)(Out + (size_t)w * D))[lane] = o;
    }
}

// ----------------------------------------------------------------
extern "C" void kernel_launch(void* const* d_in, const int* in_sizes, int n_in,
                              void* d_out, int out_size) {
    const float* x    = (const float*)d_in[0];
    const float* ctx  = (const float*)d_in[1];
    const float* W1   = (const float*)d_in[2];
    const float* b1   = (const float*)d_in[3];
    const float* W2   = (const float*)d_in[4];
    const float* b2   = (const float*)d_in[5];
    const float* Wg   = (const float*)d_in[6];
    const float* bg   = (const float*)d_in[7];
    const float* Wb   = (const float*)d_in[8];
    const int*   ei   = (const int*)d_in[9];     // int32 (JAX x64 disabled)
    float*       out  = (float*)d_out;

    int N = in_sizes[0] / D;
    int E = in_sizes[9] / 2;
    const int* esrc = ei;
    const int* edst = ei + E;

    int smemG = 4 * 128 * PS * sizeof(uint32_t);          // 139264 B
    cudaFuncSetAttribute(k_scan_gemm,
                         cudaFuncAttributeMaxDynamicSharedMemorySize, smemG);
    cudaFuncSetAttribute(k_gemm,
                         cudaFuncAttributeMaxDynamicSharedMemorySize, smemG);

    int nbS  = (N * 32 + 255) / 256;
    int nbE  = (E + 255) / 256;
    int nbN  = (N + 255) / 256;
    int gblk = (N + 127) / 128;
    long long gth = (long long)N * 32;
    int nbG  = (int)((gth + 255) / 256);

    // K1: const + input split + edge count/rank
    k_pre<<<80 + nbS + nbE, 256>>>(W1, W2, ctx, Wg, bg, Wb, x, edst, N, E, nbS);

    // K2: rowptr scan (block 0, prefix-sum only) || GEMM1
    k_scan_gemm<<<1 + gblk, 256, smemG>>>(N);

    // K3: CSR place || node finalize (cnt/dinv/zero)
    k_place_fin<<<nbE + nbN, 256>>>(esrc, edst, E, N, nbE);

    // K4: conv1 gather -> A (split bf16)
    k_gather<1><<<nbG, 256>>>(nullptr, b1, N);

    // K5: GEMM2 (fp16 out, prescaled by g_dinv)
    k_gemm<<<gblk, 256, smemG>>>(1, N);

    // K6: conv2 gather -> out
    k_gather<2><<<nbG, 256>>>(out, b2, N);
}

// round 16
// speedup vs baseline: 2.1905x; 1.0364x over previous
#include <cuda_runtime.h>
#include <cuda_fp16.h>
#include <cuda_bf16.h>
#include <math.h>
#include <stdint.h>

#define D     128
#define NMAX  50000
#define EMAX  800000
#define NPAD  (NMAX + 128)
#define PS    68          // padded smem row stride (words)

// ---- scratch (device globals; zero at load) ----
__device__ __align__(16) __half   g_T16[NPAD * D];      // message table (fp16, prescaled)
__device__ __align__(16) uint32_t g_Xh[NPAD * 64];      // split input hi pairs (also A)
__device__ __align__(16) uint32_t g_Xl[NPAD * 64];      // split input lo pairs
__device__ __align__(16) uint32_t g_Whi[2 * 8192];      // packed W hi, [m][n][kp]
__device__ __align__(16) uint32_t g_Wlo[2 * 8192];
__device__ __align__(16) int g_cntPos[NMAX];   // atomic counters; 0 on entry (K3 re-zeroes)
__device__ __align__(16) int g_cnt[NMAX];      // indeg
__device__ __align__(16) int g_rowptr[NMAX];
__device__ int   g_rank[EMAX];                 // within-destination rank
__device__ int   g_eidx[EMAX];                 // CSR source indices
__device__ float g_dinv[NMAX];
__device__ __align__(16) float g_gate[D];
__device__ __align__(16) float g_hbias[D];

// ---------------------------------------------------------------- helpers
__device__ __forceinline__ void split2f(float a, float b, uint32_t& hi, uint32_t& lo) {
    asm("cvt.rn.bf16x2.f32 %0, %1, %2;" : "=r"(hi) : "f"(b), "f"(a));
    float ha = __uint_as_float(hi << 16);
    float hb = __uint_as_float(hi & 0xffff0000u);
    float la = a - ha;
    float lb = b - hb;
    asm("cvt.rn.bf16x2.f32 %0, %1, %2;" : "=r"(lo) : "f"(lb), "f"(la));
}
__device__ __forceinline__ __half2 h2(uint32_t u) { return *(__half2*)&u; }

// ---------------------------------------------------------------- K1: const + split + count/rank
__global__ void k_pre(const float* __restrict__ W1, const float* __restrict__ W2,
                      const float* __restrict__ ctx, const float* __restrict__ Wg,
                      const float* __restrict__ bg,  const float* __restrict__ Wb,
                      const float* __restrict__ X,
                      const int* __restrict__ edst,
                      int n, int E, int nbS) {
    int blk = blockIdx.x;
    int tid = threadIdx.x;
    if (blk < 64) {                                     // W split/pack/transpose
        int idx = blk * 256 + tid;                      // 0..16383
        int m  = idx >> 13;
        int r  = idx & 8191;
        int nn = r & 127;
        int kp = r >> 7;
        const float* W = m ? W2 : W1;
        float w0 = W[(2 * kp) * D + nn];
        float w1 = W[(2 * kp + 1) * D + nn];
        uint32_t hi, lo;
        split2f(w0, w1, hi, lo);
        g_Whi[m * 8192 + nn * 64 + kp] = hi;
        g_Wlo[m * 8192 + nn * 64 + kp] = lo;
    } else if (blk < 80) {                              // hypernet
        int w    = (blk - 64) * 8 + (tid >> 5);
        int lane = tid & 31;
        float c0 = ctx[lane], c1 = ctx[lane + 32];
        float g = c0 * Wg[lane * D + w] + c1 * Wg[(lane + 32) * D + w];
        float b = c0 * Wb[lane * D + w] + c1 * Wb[(lane + 32) * D + w];
#pragma unroll
        for (int o = 16; o > 0; o >>= 1) {
            g += __shfl_down_sync(0xffffffffu, g, o);
            b += __shfl_down_sync(0xffffffffu, b, o);
        }
        if (lane == 0) {
            g_gate[w]  = 1.f / (1.f + __expf(-(g + bg[w])));
            g_hbias[w] = b;
        }
    } else if (blk < 80 + nbS) {                        // input split
        int i = (blk - 80) * 256 + tid;                 // float4 index
        if (i >= n * 32) return;
        float4 v = ((const float4*)X)[i];
        int row = i >> 5, c4 = i & 31;
        uint32_t h01, l01, h23, l23;
        split2f(v.x, v.y, h01, l01);
        split2f(v.z, v.w, h23, l23);
        *((uint2*)&g_Xh[(size_t)row * 64 + c4 * 2]) = make_uint2(h01, h23);
        *((uint2*)&g_Xl[(size_t)row * 64 + c4 * 2]) = make_uint2(l01, l23);
    } else {                                            // edge count + rank
        int i = (blk - 80 - nbS) * 256 + tid;
        if (i >= E) return;
        int d = edst[i];
        if ((unsigned)d < (unsigned)n)
            g_rank[i] = atomicAdd(&g_cntPos[d], 1);
    }
}

// ---------------------------------------------------------------- GEMM body (bf16x3 MMA, fp16 out)
__device__ __forceinline__ void mma16816(float* c, uint32_t a0, uint32_t a1,
                                         uint32_t a2, uint32_t a3,
                                         uint32_t b0, uint32_t b1) {
    asm volatile("mma.sync.aligned.m16n8k16.row.col.f32.bf16.bf16.f32 "
                 "{%0,%1,%2,%3}, {%4,%5,%6,%7}, {%8,%9}, {%0,%1,%2,%3};"
                 : "+f"(c[0]), "+f"(c[1]), "+f"(c[2]), "+f"(c[3])
                 : "r"(a0), "r"(a1), "r"(a2), "r"(a3), "r"(b0), "r"(b1));
}

// dmode 0: dinv computed inline from g_cntPos (conv1; counters read-only during K2)
// dmode 1: dinv from g_dinv (conv2)
__device__ void gemm_body(uint32_t* sm, int r0, int wsel, int dmode, int n) {
    uint32_t* Xh = sm;
    uint32_t* Xl = Xh + 128 * PS;
    uint32_t* Wh = Xl + 128 * PS;
    uint32_t* Wl = Wh + 128 * PS;
    int tid = threadIdx.x;

    const uint32_t* gwh = g_Whi + wsel * 8192;
    const uint32_t* gwl = g_Wlo + wsel * 8192;
#pragma unroll
    for (int i = 0; i < 8; i++) {
        int q  = tid + i * 256;
        int wb = q * 4;
        int nn = wb >> 6, kp = wb & 63;
        *((uint4*)&Wh[nn * PS + kp]) = ((const uint4*)gwh)[q];
        *((uint4*)&Wl[nn * PS + kp]) = ((const uint4*)gwl)[q];
    }
    const uint4* gxh = (const uint4*)g_Xh + (size_t)r0 * 16;
    const uint4* gxl = (const uint4*)g_Xl + (size_t)r0 * 16;
#pragma unroll
    for (int i = 0; i < 8; i++) {
        int q   = tid + i * 256;
        int row = q >> 4, k4 = q & 15;
        *((uint4*)&Xh[row * PS + k4 * 4]) = gxh[q];
        *((uint4*)&Xl[row * PS + k4 * 4]) = gxl[q];
    }
    __syncthreads();

    int wid  = tid >> 5;
    int lane = tid & 31;
    int g    = lane >> 2;
    int tig  = lane & 3;
    int rA   = wid * 16 + g;

    float acc[16][4];
#pragma unroll
    for (int t = 0; t < 16; t++)
#pragma unroll
        for (int c = 0; c < 4; c++) acc[t][c] = 0.f;

#pragma unroll
    for (int s = 0; s < 8; s++) {
        int kp = s * 8;
        uint32_t ah0 = Xh[rA * PS + kp + tig];
        uint32_t ah1 = Xh[(rA + 8) * PS + kp + tig];
        uint32_t ah2 = Xh[rA * PS + kp + tig + 4];
        uint32_t ah3 = Xh[(rA + 8) * PS + kp + tig + 4];
        uint32_t al0 = Xl[rA * PS + kp + tig];
        uint32_t al1 = Xl[(rA + 8) * PS + kp + tig];
        uint32_t al2 = Xl[rA * PS + kp + tig + 4];
        uint32_t al3 = Xl[(rA + 8) * PS + kp + tig + 4];
#pragma unroll
        for (int nt = 0; nt < 16; nt++) {
            int nb = nt * 8 + g;
            uint32_t bh0 = Wh[nb * PS + kp + tig];
            uint32_t bh1 = Wh[nb * PS + kp + tig + 4];
            uint32_t bl0 = Wl[nb * PS + kp + tig];
            uint32_t bl1 = Wl[nb * PS + kp + tig + 4];
            mma16816(acc[nt], ah0, ah1, ah2, ah3, bh0, bh1);
            mma16816(acc[nt], ah0, ah1, ah2, ah3, bl0, bl1);
            mma16816(acc[nt], al0, al1, al2, al3, bh0, bh1);
        }
    }

    int gr0 = r0 + wid * 16 + g;
    int gr1 = gr0 + 8;
    float d0 = 0.f, d1 = 0.f;
    if (dmode == 0) {
        if (gr0 < n) d0 = rsqrtf((float)(g_cntPos[gr0] + 1));
        if (gr1 < n) d1 = rsqrtf((float)(g_cntPos[gr1] + 1));
    } else {
        if (gr0 < n) d0 = g_dinv[gr0];
        if (gr1 < n) d1 = g_dinv[gr1];
    }
#pragma unroll
    for (int nt = 0; nt < 16; nt++) {
        int c = nt * 8 + 2 * tig;
        if (gr0 < n)
            *((__half2*)&g_T16[(size_t)gr0 * D + c]) =
                __floats2half2_rn(acc[nt][0] * d0, acc[nt][1] * d0);
        if (gr1 < n)
            *((__half2*)&g_T16[(size_t)gr1 * D + c]) =
                __floats2half2_rn(acc[nt][2] * d1, acc[nt][3] * d1);
    }
}

// ---------------------------------------------------------------- K2: rowptr-only scan (block 0) || GEMM1
__global__ void __launch_bounds__(256)
k_scan_gemm(int n) {
    extern __shared__ uint32_t sm[];
    if (blockIdx.x != 0) {
        gemm_body(sm, (blockIdx.x - 1) * 128, 0, /*dmode=*/0, n);
        return;
    }
    __shared__ int part[256];
    int tid = threadIdx.x;
    const int per = 196;                    // 256*196 >= 50000, %4==0
    int base = tid * per;
    int s = 0;
    for (int i = 0; i < per; i += 4) {
        int r = base + i;
        if (r + 3 < n) {
            int4 v = *((const int4*)&g_cntPos[r]);
            s += v.x + v.y + v.z + v.w;
        } else {
#pragma unroll
            for (int u = 0; u < 4; u++)
                if (r + u < n) s += g_cntPos[r + u];
        }
    }
    part[tid] = s;
    __syncthreads();
    for (int off = 1; off < 256; off <<= 1) {
        int v = (tid >= off) ? part[tid - off] : 0;
        __syncthreads();
        part[tid] += v;
        __syncthreads();
    }
    int run = (tid == 0) ? 0 : part[tid - 1];
    for (int i = 0; i < per; i += 4) {
        int r = base + i;
        if (r >= n) break;
        if (r + 3 < n) {
            int4 v = *((const int4*)&g_cntPos[r]);
            int4 rp;
            rp.x = run;
            rp.y = rp.x + v.x;
            rp.z = rp.y + v.y;
            rp.w = rp.z + v.z;
            run  = rp.w + v.w;
            *((int4*)&g_rowptr[r]) = rp;
        } else {
#pragma unroll
            for (int u = 0; u < 4; u++) {
                int rr = r + u;
                if (rr < n) {
                    g_rowptr[rr] = run;
                    run += g_cntPos[rr];
                }
            }
        }
    }
}

// ---------------------------------------------------------------- standalone GEMM (conv2)
__global__ void __launch_bounds__(256)
k_gemm(int wsel, int n) {
    extern __shared__ uint32_t sm[];
    gemm_body(sm, blockIdx.x * 128, wsel, /*dmode=*/1, n);
}

// ---------------------------------------------------------------- K3: CSR place || node finalize
__global__ void k_place_fin(const int* __restrict__ esrc,
                            const int* __restrict__ edst,
                            int E, int n, int nbE) {
    int blk = blockIdx.x;
    int tid = threadIdx.x;
    if (blk < nbE) {
        int i = blk * 256 + tid;
        if (i >= E) return;
        int s = esrc[i];
        int d = edst[i];
        if ((unsigned)s >= (unsigned)n || (unsigned)d >= (unsigned)n) return;
        g_eidx[g_rowptr[d] + g_rank[i]] = s;
    } else {
        int i = (blk - nbE) * 256 + tid;
        if (i < n) {
            int c = g_cntPos[i];
            g_cnt[i]  = c;
            g_dinv[i] = rsqrtf((float)(c + 1));
            g_cntPos[i] = 0;                // restore invariant for next call
        }
    }
}

// ---------------------------------------------------------------- fused gather + epilogue (fp16 T)
// HALF-WARP per row: lanes 0-15 -> row A, lanes 16-31 -> row B.
// Each lane covers 16B (8 cols) of the 256B row. Shared instructions serve 2 edges.
// T rows prescaled by dinv[src]: out[d] = epi( dinv[d] * sum_{s in d+in(d)} T[s] + b )
template <int MODE>
__global__ void __launch_bounds__(256, 6)
k_gather(float* __restrict__ Out, const float* __restrict__ bvec, int n) {
    int gtid = blockIdx.x * blockDim.x + threadIdx.x;
    int w = gtid >> 4;                      // half-warp id = row
    if (w >= n) return;
    int lane16 = threadIdx.x & 15;
    unsigned hmask = (threadIdx.x & 16) ? 0xffff0000u : 0x0000ffffu;

    int beg = g_rowptr[w];
    int cnt = g_cnt[w];
    const char* base = (const char*)g_T16 + lane16 * 16;   // per-lane 16B column slice

    float a0, a1, a2, a3, a4, a5, a6, a7;
    {   // self term
        uint4 sv = *(const uint4*)(base + ((unsigned)w << 8));
        float2 f0 = __half22float2(h2(sv.x));
        float2 f1 = __half22float2(h2(sv.y));
        float2 f2 = __half22float2(h2(sv.z));
        float2 f3 = __half22float2(h2(sv.w));
        a0 = f0.x; a1 = f0.y; a2 = f1.x; a3 = f1.y;
        a4 = f2.x; a5 = f2.y; a6 = f3.x; a7 = f3.y;
    }

    int j = 0;
    while (j < cnt) {
        int chunk = min(cnt - j, 16);
        unsigned myoff = 0;
        if (lane16 < chunk) myoff = (unsigned)g_eidx[beg + j + lane16] << 8;
        int t = 0;
        for (; t + 3 < chunk; t += 4) {
            unsigned o0 = __shfl_sync(hmask, myoff, t,     16);
            unsigned o1 = __shfl_sync(hmask, myoff, t + 1, 16);
            unsigned o2 = __shfl_sync(hmask, myoff, t + 2, 16);
            unsigned o3 = __shfl_sync(hmask, myoff, t + 3, 16);
            uint4 v0 = *(const uint4*)(base + o0);
            uint4 v1 = *(const uint4*)(base + o1);
            uint4 v2 = *(const uint4*)(base + o2);
            uint4 v3 = *(const uint4*)(base + o3);
            __half2 s0 = __hadd2(__hadd2(h2(v0.x), h2(v1.x)), __hadd2(h2(v2.x), h2(v3.x)));
            __half2 s1 = __hadd2(__hadd2(h2(v0.y), h2(v1.y)), __hadd2(h2(v2.y), h2(v3.y)));
            __half2 s2 = __hadd2(__hadd2(h2(v0.z), h2(v1.z)), __hadd2(h2(v2.z), h2(v3.z)));
            __half2 s3 = __hadd2(__hadd2(h2(v0.w), h2(v1.w)), __hadd2(h2(v2.w), h2(v3.w)));
            float2 f0 = __half22float2(s0);
            float2 f1 = __half22float2(s1);
            float2 f2 = __half22float2(s2);
            float2 f3 = __half22float2(s3);
            a0 += f0.x; a1 += f0.y; a2 += f1.x; a3 += f1.y;
            a4 += f2.x; a5 += f2.y; a6 += f3.x; a7 += f3.y;
        }
        for (; t < chunk; t++) {
            unsigned o = __shfl_sync(hmask, myoff, t, 16);
            uint4 v = *(const uint4*)(base + o);
            float2 f0 = __half22float2(h2(v.x));
            float2 f1 = __half22float2(h2(v.y));
            float2 f2 = __half22float2(h2(v.z));
            float2 f3 = __half22float2(h2(v.w));
            a0 += f0.x; a1 += f0.y; a2 += f1.x; a3 += f1.y;
            a4 += f2.x; a5 += f2.y; a6 += f3.x; a7 += f3.y;
        }
        j += chunk;
    }

    float di = g_dinv[w];
    float4 bA = ((const float4*)bvec)[lane16 * 2];
    float4 bB = ((const float4*)bvec)[lane16 * 2 + 1];
    float o0 = a0 * di + bA.x;
    float o1 = a1 * di + bA.y;
    float o2 = a2 * di + bA.z;
    float o3 = a3 * di + bA.w;
    float o4 = a4 * di + bB.x;
    float o5 = a5 * di + bB.y;
    float o6 = a6 * di + bB.z;
    float o7 = a7 * di + bB.w;
    if (MODE == 1) {
        o0 = o0 > 0.f ? o0 : 0.2f * o0;
        o1 = o1 > 0.f ? o1 : 0.2f * o1;
        o2 = o2 > 0.f ? o2 : 0.2f * o2;
        o3 = o3 > 0.f ? o3 : 0.2f * o3;
        o4 = o4 > 0.f ? o4 : 0.2f * o4;
        o5 = o5 > 0.f ? o5 : 0.2f * o5;
        o6 = o6 > 0.f ? o6 : 0.2f * o6;
        o7 = o7 > 0.f ? o7 : 0.2f * o7;
        uint32_t h01, l01, h23, l23, h45, l45, h67, l67;
        split2f(o0, o1, h01, l01);
        split2f(o2, o3, h23, l23);
        split2f(o4, o5, h45, l45);
        split2f(o6, o7, h67, l67);
        *((uint4*)&g_Xh[(size_t)w * 64 + lane16 * 4]) = make_uint4(h01, h23, h45, h67);
        *((uint4*)&g_Xl[(size_t)w * 64 + lane16 * 4]) = make_uint4(l01, l23, l45, l67);
    } else {
        float4 gA = ((const float4*)g_gate)[lane16 * 2];
        float4 gB = ((const float4*)g_gate)[lane16 * 2 + 1];
        float4 hA = ((const float4*)g_hbias)[lane16 * 2];
        float4 hB = ((const float4*)g_hbias)[lane16 * 2 + 1];
        float4 r0 = make_float4(o0 * gA.x + hA.x, o1 * gA.y + hA.y,
                                o2 * gA.z + hA.z, o3 * gA.w + hA.w);
        float4 r1 = make_float4(o4 * gB.x + hB.x, o5 * gB.y + hB.y,
                                o6 * gB.z + hB.z, o7 * gB.w + hB.w);
        ((float4*)(Out + (size_t)w * D))[lane16 * 2]     = r0;
        ((float4*)(Out + (size_t)w * D))[lane16 * 2 + 1] = r1;
    }
}

// ----------------------------------------------------------------
extern "C" void kernel_launch(void* const* d_in, const int* in_sizes, int n_in,
                              void* d_out, int out_size) {
    const float* x    = (const float*)d_in[0];
    const float* ctx  = (const float*)d_in[1];
    const float* W1   = (const float*)d_in[2];
    const float* b1   = (const float*)d_in[3];
    const float* W2   = (const float*)d_in[4];
    const float* b2   = (const float*)d_in[5];
    const float* Wg   = (const float*)d_in[6];
    const float* bg   = (const float*)d_in[7];
    const float* Wb   = (const float*)d_in[8];
    const int*   ei   = (const int*)d_in[9];     // int32 (JAX x64 disabled)
    float*       out  = (float*)d_out;

    int N = in_sizes[0] / D;
    int E = in_sizes[9] / 2;
    const int* esrc = ei;
    const int* edst = ei + E;

    int smemG = 4 * 128 * PS * sizeof(uint32_t);          // 139264 B
    cudaFuncSetAttribute(k_scan_gemm,
                         cudaFuncAttributeMaxDynamicSharedMemorySize, smemG);
    cudaFuncSetAttribute(k_gemm,
                         cudaFuncAttributeMaxDynamicSharedMemorySize, smemG);

    int nbS  = (N * 32 + 255) / 256;
    int nbE  = (E + 255) / 256;
    int nbN  = (N + 255) / 256;
    int gblk = (N + 127) / 128;
    long long gth = (long long)N * 16;            // one HALF-warp per node
    int nbG  = (int)((gth + 255) / 256);

    // K1: const + input split + edge count/rank
    k_pre<<<80 + nbS + nbE, 256>>>(W1, W2, ctx, Wg, bg, Wb, x, edst, N, E, nbS);

    // K2: rowptr scan (block 0, prefix-sum only) || GEMM1
    k_scan_gemm<<<1 + gblk, 256, smemG>>>(N);

    // K3: CSR place || node finalize (cnt/dinv/zero)
    k_place_fin<<<nbE + nbN, 256>>>(esrc, edst, E, N, nbE);

    // K4: conv1 gather -> A (split bf16)
    k_gather<1><<<nbG, 256>>>(nullptr, b1, N);

    // K5: GEMM2 (fp16 out, prescaled by g_dinv)
    k_gemm<<<gblk, 256, smemG>>>(1, N);

    // K6: conv2 gather -> out
    k_gather<2><<<nbG, 256>>>(out, b2, N);
}